// round 2
// baseline (speedup 1.0000x reference)
#include <cuda_runtime.h>
#include <math.h>

#define BATCH 8
#define SEQ 1600
#define IN_DIM 256
#define DMODEL 512
#define NHEAD 8
#define HDIM 64
#define NJOINT 25
#define BH (BATCH*NHEAD)                 // 64
#define OUT_ELEMS (BATCH*SEQ*DMODEL)     // 6,553,600
#define PATT_ELEMS ((size_t)BH*SEQ*SEQ)  // 163,840,000

__device__ float g_q[BH*SEQ*HDIM];
__device__ float g_k[BH*SEQ*HDIM];
__device__ float g_v[BH*SEQ*HDIM];
__device__ float g_rowinv[BH*SEQ];
__device__ float g_scores_fallback[PATT_ELEMS];

// ---------------------------------------------------------------------------
// K1: QKV projection. 128x128 tile, 256 threads, 8x8 per thread, KC=32.
// out[r,c] = x[r,:] @ W[:,c] + b[c] (+ReLU for V); stored [b,h,s,d].
// ---------------------------------------------------------------------------
__global__ __launch_bounds__(256, 2) void qkv_kernel(
    const float* __restrict__ x,
    const float* __restrict__ wq, const float* __restrict__ bq,
    const float* __restrict__ wk, const float* __restrict__ bk,
    const float* __restrict__ wv, const float* __restrict__ bv)
{
    const float* W; const float* bias; float* dst; bool do_relu;
    int z = blockIdx.z;
    if (z == 0)      { W = wq; bias = bq; dst = g_q; do_relu = false; }
    else if (z == 1) { W = wk; bias = bk; dst = g_k; do_relu = false; }
    else             { W = wv; bias = bv; dst = g_v; do_relu = true;  }

    __shared__ float xsT[32][132];   // [k][m] transposed
    __shared__ float ws[32][132];    // [k][n]

    const int t  = threadIdx.x;
    const int tx = t & 15, ty = t >> 4;
    const int rowBase = blockIdx.y * 128;
    const int nBase   = blockIdx.x * 128;

    float acc[8][8] = {};

    for (int k0 = 0; k0 < IN_DIM; k0 += 32) {
        float4 av[4], bv4[4];
        #pragma unroll
        for (int p = 0; p < 4; p++) {
            int idx = t + p * 256;
            int r   = idx >> 3;           // 0..127
            int cg  = (idx & 7) * 4;      // 0..28
            av[p] = *(const float4*)&x[(size_t)(rowBase + r) * IN_DIM + k0 + cg];
            int kk = idx >> 5;            // 0..31
            int c  = (idx & 31) * 4;      // 0..124
            bv4[p] = *(const float4*)&W[(size_t)(k0 + kk) * DMODEL + nBase + c];
        }
        __syncthreads();
        #pragma unroll
        for (int p = 0; p < 4; p++) {
            int idx = t + p * 256;
            int r   = idx >> 3;
            int cg  = (idx & 7) * 4;
            xsT[cg + 0][r] = av[p].x; xsT[cg + 1][r] = av[p].y;
            xsT[cg + 2][r] = av[p].z; xsT[cg + 3][r] = av[p].w;
            int kk = idx >> 5;
            int c  = (idx & 31) * 4;
            *(float4*)&ws[kk][c] = bv4[p];
        }
        __syncthreads();
        #pragma unroll
        for (int kk = 0; kk < 32; kk++) {
            float4 A0 = *(float4*)&xsT[kk][ty * 8];
            float4 A1 = *(float4*)&xsT[kk][ty * 8 + 4];
            float4 B0 = *(float4*)&ws[kk][tx * 8];
            float4 B1 = *(float4*)&ws[kk][tx * 8 + 4];
            float ar[8] = {A0.x,A0.y,A0.z,A0.w,A1.x,A1.y,A1.z,A1.w};
            float br[8] = {B0.x,B0.y,B0.z,B0.w,B1.x,B1.y,B1.z,B1.w};
            #pragma unroll
            for (int i = 0; i < 8; i++)
                #pragma unroll
                for (int j = 0; j < 8; j++)
                    acc[i][j] += ar[i] * br[j];
        }
    }

    float bb[8];
    #pragma unroll
    for (int j = 0; j < 8; j++) bb[j] = bias[nBase + tx * 8 + j];
    const int h  = (nBase + tx * 8) >> 6;
    const int ch = (nBase + tx * 8) & 63;
    #pragma unroll
    for (int i = 0; i < 8; i++) {
        int r  = rowBase + ty * 8 + i;
        int b_ = r / SEQ, s_ = r % SEQ;
        float v[8];
        #pragma unroll
        for (int j = 0; j < 8; j++) {
            v[j] = acc[i][j] + bb[j];
            if (do_relu) v[j] = fmaxf(v[j], 0.f);
        }
        float* base = &dst[((size_t)(b_ * NHEAD + h) * SEQ + s_) * HDIM + ch];
        *(float4*)&base[0] = make_float4(v[0], v[1], v[2], v[3]);
        *(float4*)&base[4] = make_float4(v[4], v[5], v[6], v[7]);
    }
}

// ---------------------------------------------------------------------------
// K2: e = exp(masked(Q.K^T)/8). 128x128 tile, 8x8/thread, depth 64 in 2 chunks.
// Masked entries write 0 (exp(NEG)=0). Ragged edges clamped/predicated.
// ---------------------------------------------------------------------------
__global__ __launch_bounds__(256, 2) void scores_kernel(float* __restrict__ Pext, int use_ext)
{
    float* P = use_ext ? Pext : g_scores_fallback;
    const int bh    = blockIdx.z;
    const int qBase = blockIdx.y * 128;
    const int kBase = blockIdx.x * 128;
    const float* Q = g_q + (size_t)bh * SEQ * HDIM;
    const float* K = g_k + (size_t)bh * SEQ * HDIM;

    __shared__ float qsT[32][132];  // [d][q]
    __shared__ float ksT[32][132];  // [d][k]

    const int t = threadIdx.x;
    const int tx = t & 15, ty = t >> 4;

    float acc[8][8] = {};

    for (int d0 = 0; d0 < HDIM; d0 += 32) {
        float4 qv[4], kv[4];
        #pragma unroll
        for (int p = 0; p < 4; p++) {
            int idx = t + p * 256;
            int r   = idx >> 3;
            int cg  = (idx & 7) * 4;
            int qr = min(qBase + r, SEQ - 1);
            int kr = min(kBase + r, SEQ - 1);
            qv[p] = *(const float4*)&Q[(size_t)qr * HDIM + d0 + cg];
            kv[p] = *(const float4*)&K[(size_t)kr * HDIM + d0 + cg];
        }
        __syncthreads();
        #pragma unroll
        for (int p = 0; p < 4; p++) {
            int idx = t + p * 256;
            int r   = idx >> 3;
            int cg  = (idx & 7) * 4;
            qsT[cg + 0][r] = qv[p].x; qsT[cg + 1][r] = qv[p].y;
            qsT[cg + 2][r] = qv[p].z; qsT[cg + 3][r] = qv[p].w;
            ksT[cg + 0][r] = kv[p].x; ksT[cg + 1][r] = kv[p].y;
            ksT[cg + 2][r] = kv[p].z; ksT[cg + 3][r] = kv[p].w;
        }
        __syncthreads();
        #pragma unroll
        for (int kk = 0; kk < 32; kk++) {
            float4 A0 = *(float4*)&qsT[kk][ty * 8];
            float4 A1 = *(float4*)&qsT[kk][ty * 8 + 4];
            float4 B0 = *(float4*)&ksT[kk][tx * 8];
            float4 B1 = *(float4*)&ksT[kk][tx * 8 + 4];
            float ar[8] = {A0.x,A0.y,A0.z,A0.w,A1.x,A1.y,A1.z,A1.w};
            float br[8] = {B0.x,B0.y,B0.z,B0.w,B1.x,B1.y,B1.z,B1.w};
            #pragma unroll
            for (int i = 0; i < 8; i++)
                #pragma unroll
                for (int j = 0; j < 8; j++)
                    acc[i][j] += ar[i] * br[j];
        }
        __syncthreads();
    }

    int kg[8], fk[8];
    #pragma unroll
    for (int j = 0; j < 8; j++) { kg[j] = kBase + tx * 8 + j; fk[j] = kg[j] / NJOINT; }

    #pragma unroll
    for (int i = 0; i < 8; i++) {
        int qg = qBase + ty * 8 + i;
        if (qg >= SEQ) continue;
        int fq = qg / NJOINT;
        float v[8];
        #pragma unroll
        for (int j = 0; j < 8; j++) {
            bool allow = (fq != fk[j]) || (qg == kg[j]);
            v[j] = allow ? __expf(acc[i][j] * 0.125f) : 0.f;
        }
        float* row = &P[((size_t)bh * SEQ + qg) * SEQ];
        if (kg[0] < SEQ) *(float4*)&row[kg[0]] = make_float4(v[0], v[1], v[2], v[3]);
        if (kg[4] < SEQ) *(float4*)&row[kg[4]] = make_float4(v[4], v[5], v[6], v[7]);
    }
}

// ---------------------------------------------------------------------------
// K3: row sums of e -> 1/sum. One warp per row, float4 reads.
// ---------------------------------------------------------------------------
__global__ __launch_bounds__(256) void rowsum_kernel(const float* __restrict__ Pext, int use_ext)
{
    const float* P = use_ext ? Pext : g_scores_fallback;
    int row  = blockIdx.x * 8 + (threadIdx.x >> 5);
    int lane = threadIdx.x & 31;
    const float* pr = P + (size_t)row * SEQ;

    float s = 0.f;
    for (int k = lane * 4; k < SEQ; k += 128) {
        float4 v = *(const float4*)&pr[k];
        s += (v.x + v.y) + (v.z + v.w);
    }
    #pragma unroll
    for (int off = 16; off; off >>= 1)
        s += __shfl_xor_sync(0xffffffffu, s, off);
    if (lane == 0) g_rowinv[row] = 1.f / s;
}

// ---------------------------------------------------------------------------
// K4: p = e/sum (write in place) + out = P @ V.
// 128(q) x 64(d) tile, 128 threads, 8x8/thread, KC=32, 50 k-iterations.
// ---------------------------------------------------------------------------
__global__ __launch_bounds__(128, 4) void out_kernel(float* __restrict__ Pext, int use_ext,
                                                     float* __restrict__ out)
{
    float* P = use_ext ? Pext : g_scores_fallback;
    const int bh    = blockIdx.y;
    const int qBase = blockIdx.x * 128;
    const float* V = g_v + (size_t)bh * SEQ * HDIM;
    float* Pr = P + (size_t)bh * SEQ * SEQ;

    __shared__ float esT[32][132];  // [k][q]
    __shared__ float vs[32][68];    // [k][d]
    __shared__ float rinv[128];

    const int t = threadIdx.x;
    const int tx = t & 7, ty = t >> 3;

    rinv[t] = g_rowinv[bh * SEQ + min(qBase + t, SEQ - 1)];

    float acc[8][8] = {};

    for (int k0 = 0; k0 < SEQ; k0 += 32) {
        __syncthreads();   // first iter: covers rinv; later: smem reuse guard
        #pragma unroll
        for (int p = 0; p < 8; p++) {
            int idx = t + p * 128;
            int r   = idx >> 3;           // q row 0..127
            int cg  = (idx & 7) * 4;      // k offset 0..28
            int qg  = qBase + r;
            int qr  = min(qg, SEQ - 1);
            float4 e4 = *(const float4*)&Pr[(size_t)qr * SEQ + k0 + cg];
            float inv = rinv[r];
            float4 pv = make_float4(e4.x * inv, e4.y * inv, e4.z * inv, e4.w * inv);
            if (qg < SEQ) *(float4*)&Pr[(size_t)qg * SEQ + k0 + cg] = pv;  // final p
            esT[cg + 0][r] = pv.x; esT[cg + 1][r] = pv.y;
            esT[cg + 2][r] = pv.z; esT[cg + 3][r] = pv.w;
        }
        #pragma unroll
        for (int p = 0; p < 4; p++) {
            int idx = t + p * 128;
            int vr  = idx >> 4;           // 0..31
            int cg  = (idx & 15) * 4;     // 0..60
            *(float4*)&vs[vr][cg] = *(const float4*)&V[(size_t)(k0 + vr) * HDIM + cg];
        }
        __syncthreads();
        #pragma unroll
        for (int kk = 0; kk < 32; kk++) {
            float4 A0 = *(float4*)&esT[kk][ty * 8];
            float4 A1 = *(float4*)&esT[kk][ty * 8 + 4];
            float4 B0 = *(float4*)&vs[kk][tx * 8];
            float4 B1 = *(float4*)&vs[kk][tx * 8 + 4];
            float ar[8] = {A0.x,A0.y,A0.z,A0.w,A1.x,A1.y,A1.z,A1.w};
            float br[8] = {B0.x,B0.y,B0.z,B0.w,B1.x,B1.y,B1.z,B1.w};
            #pragma unroll
            for (int i = 0; i < 8; i++)
                #pragma unroll
                for (int j = 0; j < 8; j++)
                    acc[i][j] += ar[i] * br[j];
        }
    }

    const int b_ = bh / NHEAD, h_ = bh % NHEAD;
    #pragma unroll
    for (int i = 0; i < 8; i++) {
        int s_ = qBase + ty * 8 + i;
        if (s_ >= SEQ) continue;
        float* base = &out[((size_t)b_ * SEQ + s_) * DMODEL + h_ * HDIM + tx * 8];
        *(float4*)&base[0] = make_float4(acc[i][0], acc[i][1], acc[i][2], acc[i][3]);
        *(float4*)&base[4] = make_float4(acc[i][4], acc[i][5], acc[i][6], acc[i][7]);
    }
}

// ---------------------------------------------------------------------------
extern "C" void kernel_launch(void* const* d_in, const int* in_sizes, int n_in,
                              void* d_out, int out_size)
{
    const float* x  = (const float*)d_in[0];
    const float* wq = (const float*)d_in[1];
    const float* bq = (const float*)d_in[2];
    const float* wk = (const float*)d_in[3];
    const float* bk = (const float*)d_in[4];
    const float* wv = (const float*)d_in[5];
    const float* bv = (const float*)d_in[6];
    float* out = (float*)d_out;

    int use_ext = ((size_t)out_size >= OUT_ELEMS + PATT_ELEMS) ? 1 : 0;
    float* Pext = out + OUT_ELEMS;

    {   // K1: QKV
        dim3 grid(DMODEL / 128, (BATCH * SEQ) / 128, 3);
        qkv_kernel<<<grid, 256>>>(x, wq, bq, wk, bk, wv, bv);
    }
    {   // K2: e = exp(masked scores)
        dim3 grid((SEQ + 127) / 128, (SEQ + 127) / 128, BH);
        scores_kernel<<<grid, 256>>>(Pext, use_ext);
    }
    {   // K3: row sums
        rowsum_kernel<<<(BH * SEQ) / 8, 256>>>(Pext, use_ext);
    }
    {   // K4: normalize + p write + P@V
        dim3 grid((SEQ + 127) / 128, BH);
        out_kernel<<<grid, 128>>>(Pext, use_ext, out);
    }
}

// round 4
// speedup vs baseline: 1.2008x; 1.2008x over previous
#include <cuda_runtime.h>
#include <cuda_bf16.h>
#include <math.h>
#include <stdint.h>

#define BATCH 8
#define SEQ 1600
#define IN_DIM 256
#define DMODEL 512
#define NHEAD 8
#define HDIM 64
#define NJOINT 25
#define BH (BATCH*NHEAD)                 // 64
#define OUT_ELEMS (BATCH*SEQ*DMODEL)     // 6,553,600
#define PATT_ELEMS ((size_t)BH*SEQ*SEQ)  // 163,840,000

// scratch (__device__ globals; no allocation allowed)
__device__ __nv_bfloat16 g_qhi[BH*SEQ*HDIM];
__device__ __nv_bfloat16 g_qlo[BH*SEQ*HDIM];
__device__ __nv_bfloat16 g_khi[BH*SEQ*HDIM];
__device__ __nv_bfloat16 g_klo[BH*SEQ*HDIM];
__device__ __nv_bfloat16 g_vthi[BH*HDIM*SEQ];   // transposed: [bh][d][s]
__device__ __nv_bfloat16 g_vtlo[BH*HDIM*SEQ];
__device__ float g_rowinv[BH*SEQ];
__device__ float g_scores_fallback[PATT_ELEMS];

#define SW(o) ((o) ^ (((o) >> 3) & 0x70))

__device__ __forceinline__ uint32_t smem_u32(const void* p) {
    uint32_t a;
    asm("{ .reg .u64 t; cvta.to.shared.u64 t, %1; cvt.u32.u64 %0, t; }" : "=r"(a) : "l"(p));
    return a;
}
__device__ __forceinline__ void ldsm4(uint32_t* r, uint32_t addr) {
    asm volatile("ldmatrix.sync.aligned.m8n8.x4.shared.b16 {%0,%1,%2,%3}, [%4];"
                 : "=r"(r[0]), "=r"(r[1]), "=r"(r[2]), "=r"(r[3]) : "r"(addr));
}
__device__ __forceinline__ void mma16816(float* c, const uint32_t* a, const uint32_t* b) {
    asm volatile("mma.sync.aligned.m16n8k16.row.col.f32.bf16.bf16.f32 "
                 "{%0,%1,%2,%3}, {%4,%5,%6,%7}, {%8,%9}, {%0,%1,%2,%3};"
                 : "+f"(c[0]), "+f"(c[1]), "+f"(c[2]), "+f"(c[3])
                 : "r"(a[0]), "r"(a[1]), "r"(a[2]), "r"(a[3]), "r"(b[0]), "r"(b[1]));
}

// ---------------------------------------------------------------------------
// K1: QKV projection (fp32 SIMT GEMM 128x128 tile). Epilogue emits bf16 hi/lo:
//   Q,K -> [bh, s, d];  V(+ReLU) -> transposed [bh, d, s].
// ---------------------------------------------------------------------------
__global__ __launch_bounds__(256, 2) void qkv_kernel(
    const float* __restrict__ x,
    const float* __restrict__ wq, const float* __restrict__ bq,
    const float* __restrict__ wk, const float* __restrict__ bk,
    const float* __restrict__ wv, const float* __restrict__ bv)
{
    const float* W; const float* bias; int z = blockIdx.z;
    if (z == 0)      { W = wq; bias = bq; }
    else if (z == 1) { W = wk; bias = bk; }
    else             { W = wv; bias = bv; }

    __shared__ float xsT[32][132];
    __shared__ float ws[32][132];

    const int t  = threadIdx.x;
    const int tx = t & 15, ty = t >> 4;
    const int rowBase = blockIdx.y * 128;
    const int nBase   = blockIdx.x * 128;

    float acc[8][8] = {};

    for (int k0 = 0; k0 < IN_DIM; k0 += 32) {
        float4 av[4], bv4[4];
        #pragma unroll
        for (int p = 0; p < 4; p++) {
            int idx = t + p * 256;
            int r   = idx >> 3;
            int cg  = (idx & 7) * 4;
            av[p] = *(const float4*)&x[(size_t)(rowBase + r) * IN_DIM + k0 + cg];
            int kk = idx >> 5;
            int c  = (idx & 31) * 4;
            bv4[p] = *(const float4*)&W[(size_t)(k0 + kk) * DMODEL + nBase + c];
        }
        __syncthreads();
        #pragma unroll
        for (int p = 0; p < 4; p++) {
            int idx = t + p * 256;
            int r   = idx >> 3;
            int cg  = (idx & 7) * 4;
            xsT[cg + 0][r] = av[p].x; xsT[cg + 1][r] = av[p].y;
            xsT[cg + 2][r] = av[p].z; xsT[cg + 3][r] = av[p].w;
            int kk = idx >> 5;
            int c  = (idx & 31) * 4;
            *(float4*)&ws[kk][c] = bv4[p];
        }
        __syncthreads();
        #pragma unroll
        for (int kk = 0; kk < 32; kk++) {
            float4 A0 = *(float4*)&xsT[kk][ty * 8];
            float4 A1 = *(float4*)&xsT[kk][ty * 8 + 4];
            float4 B0 = *(float4*)&ws[kk][tx * 8];
            float4 B1 = *(float4*)&ws[kk][tx * 8 + 4];
            float ar[8] = {A0.x,A0.y,A0.z,A0.w,A1.x,A1.y,A1.z,A1.w};
            float br[8] = {B0.x,B0.y,B0.z,B0.w,B1.x,B1.y,B1.z,B1.w};
            #pragma unroll
            for (int i = 0; i < 8; i++)
                #pragma unroll
                for (int j = 0; j < 8; j++)
                    acc[i][j] += ar[i] * br[j];
        }
    }

    float bb[8];
    #pragma unroll
    for (int j = 0; j < 8; j++) bb[j] = bias[nBase + tx * 8 + j];
    const int h  = (nBase + tx * 8) >> 6;
    const int ch = (nBase + tx * 8) & 63;

    if (z < 2) {
        __nv_bfloat16* DH = (z == 0) ? g_qhi : g_khi;
        __nv_bfloat16* DL = (z == 0) ? g_qlo : g_klo;
        #pragma unroll
        for (int i = 0; i < 8; i++) {
            int r  = rowBase + ty * 8 + i;
            int b_ = r / SEQ, s_ = r % SEQ;
            __align__(16) __nv_bfloat16 hb[8], lb[8];
            #pragma unroll
            for (int j = 0; j < 8; j++) {
                float v = acc[i][j] + bb[j];
                hb[j] = __float2bfloat16(v);
                lb[j] = __float2bfloat16(v - __bfloat162float(hb[j]));
            }
            size_t base = ((size_t)(b_ * NHEAD + h) * SEQ + s_) * HDIM + ch;
            *(uint4*)&DH[base] = *(uint4*)hb;
            *(uint4*)&DL[base] = *(uint4*)lb;
        }
    } else {
        int r0 = rowBase + ty * 8;
        int b_ = r0 / SEQ, s0 = r0 % SEQ;   // 8-row group never splits a batch
        #pragma unroll
        for (int j = 0; j < 8; j++) {
            __align__(16) __nv_bfloat16 hb[8], lb[8];
            #pragma unroll
            for (int i = 0; i < 8; i++) {
                float v = fmaxf(acc[i][j] + bb[j], 0.f);   // ReLU
                hb[i] = __float2bfloat16(v);
                lb[i] = __float2bfloat16(v - __bfloat162float(hb[i]));
            }
            size_t base = ((size_t)(b_ * NHEAD + h) * HDIM + (ch + j)) * SEQ + s0;
            *(uint4*)&g_vthi[base] = *(uint4*)hb;
            *(uint4*)&g_vtlo[base] = *(uint4*)lb;
        }
    }
}

// ---------------------------------------------------------------------------
// K2 fused: HMMA (mma.sync bf16, split hi/lo) attention.
// Block = (bh, 128 q rows), 256 threads = 8 warps; warp w owns q rows
// [qBase+16w, +16). Loop over 25 key tiles of 64:
//   S = Q K^T (3 HMMA terms) -> mask+exp in regs -> e
//   e written raw to P, rowsum accumulated, e repacked as A-frags (bf16 hi/lo)
//   O += e V^T (3 HMMA terms), accumulated in registers.
// Epilogue: out = O / rowsum; rowinv saved for the scale pass.
// ---------------------------------------------------------------------------
__global__ __launch_bounds__(256) void attn_kernel(
    float* __restrict__ Pext, int use_ext, float* __restrict__ out)
{
    __shared__ __align__(16) __nv_bfloat16 skh[64*64];
    __shared__ __align__(16) __nv_bfloat16 skl[64*64];
    __shared__ __align__(16) __nv_bfloat16 svh[64*64];
    __shared__ __align__(16) __nv_bfloat16 svl[64*64];

    float* P = use_ext ? Pext : g_scores_fallback;
    const int tid = threadIdx.x, w = tid >> 5, lane = tid & 31;
    const int bh = blockIdx.y;
    const int qBase = blockIdx.x * 128;

    const int row0 = qBase + w * 16 + (lane >> 2);
    const int row1 = row0 + 8;
    const int c2   = (lane & 3) * 2;
    const int fq0 = row0 / NJOINT, fq1 = row1 / NJOINT;

    const __nv_bfloat16* qh = g_qhi + (size_t)bh * SEQ * HDIM;
    const __nv_bfloat16* ql = g_qlo + (size_t)bh * SEQ * HDIM;
    const __nv_bfloat16* kh = g_khi + (size_t)bh * SEQ * HDIM;
    const __nv_bfloat16* kl = g_klo + (size_t)bh * SEQ * HDIM;
    const __nv_bfloat16* vh = g_vthi + (size_t)bh * HDIM * SEQ;
    const __nv_bfloat16* vl = g_vtlo + (size_t)bh * HDIM * SEQ;

    // Q A-fragments, resident all kernel (hi & lo). qfh[t] covers d=[16t,16t+16)
    uint32_t qfh[4][4], qfl[4][4];
    {
        int r0c = min(row0, SEQ - 1), r1c = min(row1, SEQ - 1);
        #pragma unroll
        for (int t = 0; t < 4; t++) {
            qfh[t][0] = *(const uint32_t*)&qh[(size_t)r0c * HDIM + t*16 + c2];
            qfh[t][1] = *(const uint32_t*)&qh[(size_t)r1c * HDIM + t*16 + c2];
            qfh[t][2] = *(const uint32_t*)&qh[(size_t)r0c * HDIM + t*16 + 8 + c2];
            qfh[t][3] = *(const uint32_t*)&qh[(size_t)r1c * HDIM + t*16 + 8 + c2];
            qfl[t][0] = *(const uint32_t*)&ql[(size_t)r0c * HDIM + t*16 + c2];
            qfl[t][1] = *(const uint32_t*)&ql[(size_t)r1c * HDIM + t*16 + c2];
            qfl[t][2] = *(const uint32_t*)&ql[(size_t)r0c * HDIM + t*16 + 8 + c2];
            qfl[t][3] = *(const uint32_t*)&ql[(size_t)r1c * HDIM + t*16 + 8 + c2];
        }
    }

    const uint32_t skh_b = smem_u32(skh), skl_b = smem_u32(skl);
    const uint32_t svh_b = smem_u32(svh), svl_b = smem_u32(svl);

    float oc[8][4];
    #pragma unroll
    for (int j = 0; j < 8; j++) { oc[j][0]=0.f; oc[j][1]=0.f; oc[j][2]=0.f; oc[j][3]=0.f; }
    float rsum0 = 0.f, rsum1 = 0.f;

    float* prow0 = P + ((size_t)bh * SEQ + row0) * SEQ;   // deref only if row<SEQ
    float* prow1 = P + ((size_t)bh * SEQ + row1) * SEQ;

    // ldmatrix source addresses (fixed per thread): row = lane&7 within frag,
    // chunk = (lane>>3)*16 bytes.
    const int lrow = lane & 7;
    const int lcb  = (lane >> 3) * 16;

    for (int kt = 0; kt < 25; kt++) {
        const int k0 = kt * 64;
        __syncthreads();
        // stage K (hi/lo) rows [k0,k0+64) x 64d and Vt (hi/lo) rows d x keys
        for (int i = tid; i < 2048; i += 256) {
            int buf = i >> 9, rem = i & 511;
            int r = rem >> 3, cb = (rem & 7) * 16;
            uint4 v;
            if (buf == 0)      v = *(const uint4*)((const char*)&kh[(size_t)(k0 + r) * HDIM] + cb);
            else if (buf == 1) v = *(const uint4*)((const char*)&kl[(size_t)(k0 + r) * HDIM] + cb);
            else if (buf == 2) v = *(const uint4*)((const char*)&vh[(size_t)r * SEQ + k0] + cb);
            else               v = *(const uint4*)((const char*)&vl[(size_t)r * SEQ + k0] + cb);
            char* dst = (buf == 0) ? (char*)skh : (buf == 1) ? (char*)skl
                      : (buf == 2) ? (char*)svh : (char*)svl;
            *(uint4*)(dst + SW(r * 128 + cb)) = v;
        }
        __syncthreads();

        // ---- S = Q K^T (+hi/lo cross terms), 8 n-frags of 8 keys ----
        float sc[8][4];
        #pragma unroll
        for (int jp = 0; jp < 4; jp++) {
            const int j0 = jp * 2, j1 = jp * 2 + 1;
            uint32_t b0h[8], b0l[8], b1h[8], b1l[8];
            {
                uint32_t a = SW((j0 * 8 + lrow) * 128 + lcb);
                ldsm4(b0h, skh_b + a); ldsm4(b0h + 4, skh_b + (a ^ 64));
                ldsm4(b0l, skl_b + a); ldsm4(b0l + 4, skl_b + (a ^ 64));
                uint32_t b = SW((j1 * 8 + lrow) * 128 + lcb);
                ldsm4(b1h, skh_b + b); ldsm4(b1h + 4, skh_b + (b ^ 64));
                ldsm4(b1l, skl_b + b); ldsm4(b1l + 4, skl_b + (b ^ 64));
            }
            float c0[4] = {0.f,0.f,0.f,0.f}, c1[4] = {0.f,0.f,0.f,0.f};
            #pragma unroll
            for (int t = 0; t < 4; t++) {
                mma16816(c0, qfh[t], b0h + 2*t);
                mma16816(c1, qfh[t], b1h + 2*t);
                mma16816(c0, qfh[t], b0l + 2*t);
                mma16816(c1, qfh[t], b1l + 2*t);
                mma16816(c0, qfl[t], b0h + 2*t);
                mma16816(c1, qfl[t], b1h + 2*t);
            }
            #pragma unroll
            for (int u = 0; u < 4; u++) { sc[j0][u] = c0[u]; sc[j1][u] = c1[u]; }
        }

        // ---- mask + exp + rowsum + p-store + repack to A-frags ----
        uint32_t eah[4][4], eal[4][4];
        #pragma unroll
        for (int j = 0; j < 8; j++) {
            int kcol = k0 + j * 8 + c2;
            int fk0 = kcol / NJOINT, fk1 = (kcol + 1) / NJOINT;
            bool a00 = (fq0 != fk0) || (row0 == kcol);
            bool a01 = (fq0 != fk1) || (row0 == kcol + 1);
            bool a10 = (fq1 != fk0) || (row1 == kcol);
            bool a11 = (fq1 != fk1) || (row1 == kcol + 1);
            float e00 = a00 ? __expf(sc[j][0] * 0.125f) : 0.f;
            float e01 = a01 ? __expf(sc[j][1] * 0.125f) : 0.f;
            float e10 = a10 ? __expf(sc[j][2] * 0.125f) : 0.f;
            float e11 = a11 ? __expf(sc[j][3] * 0.125f) : 0.f;
            rsum0 += e00 + e01;
            rsum1 += e10 + e11;
            if (row0 < SEQ) *(float2*)&prow0[kcol] = make_float2(e00, e01);
            if (row1 < SEQ) *(float2*)&prow1[kcol] = make_float2(e10, e11);
            __nv_bfloat162 h0 = __floats2bfloat162_rn(e00, e01);
            __nv_bfloat162 h1 = __floats2bfloat162_rn(e10, e11);
            __nv_bfloat162 l0 = __floats2bfloat162_rn(e00 - __bfloat162float(h0.x),
                                                      e01 - __bfloat162float(h0.y));
            __nv_bfloat162 l1 = __floats2bfloat162_rn(e10 - __bfloat162float(h1.x),
                                                      e11 - __bfloat162float(h1.y));
            int t = j >> 1, odd = (j & 1) * 2;
            eah[t][odd + 0] = *(uint32_t*)&h0; eah[t][odd + 1] = *(uint32_t*)&h1;
            eal[t][odd + 0] = *(uint32_t*)&l0; eal[t][odd + 1] = *(uint32_t*)&l1;
        }

        // ---- O += e V^T, 8 d-frags ----
        #pragma unroll
        for (int jp = 0; jp < 4; jp++) {
            const int j0 = jp * 2, j1 = jp * 2 + 1;
            uint32_t b0h[8], b0l[8], b1h[8], b1l[8];
            {
                uint32_t a = SW((j0 * 8 + lrow) * 128 + lcb);
                ldsm4(b0h, svh_b + a); ldsm4(b0h + 4, svh_b + (a ^ 64));
                ldsm4(b0l, svl_b + a); ldsm4(b0l + 4, svl_b + (a ^ 64));
                uint32_t b = SW((j1 * 8 + lrow) * 128 + lcb);
                ldsm4(b1h, svh_b + b); ldsm4(b1h + 4, svh_b + (b ^ 64));
                ldsm4(b1l, svl_b + b); ldsm4(b1l + 4, svl_b + (b ^ 64));
            }
            #pragma unroll
            for (int t = 0; t < 4; t++) {
                mma16816(oc[j0], eah[t], b0h + 2*t);
                mma16816(oc[j1], eah[t], b1h + 2*t);
                mma16816(oc[j0], eah[t], b0l + 2*t);
                mma16816(oc[j1], eah[t], b1l + 2*t);
                mma16816(oc[j0], eal[t], b0h + 2*t);
                mma16816(oc[j1], eal[t], b1h + 2*t);
            }
        }
    }

    // rowsum reduce across the 4 lanes sharing a row (butterfly -> all lanes)
    #pragma unroll
    for (int off = 1; off < 4; off <<= 1) {
        rsum0 += __shfl_xor_sync(0xffffffffu, rsum0, off);
        rsum1 += __shfl_xor_sync(0xffffffffu, rsum1, off);
    }
    float inv0 = 1.f / rsum0, inv1 = 1.f / rsum1;
    if ((lane & 3) == 0) {
        if (row0 < SEQ) g_rowinv[bh * SEQ + row0] = inv0;
        if (row1 < SEQ) g_rowinv[bh * SEQ + row1] = inv1;
    }

    const int b_ = bh >> 3, h_ = bh & 7;
    float* ob0 = out + ((size_t)b_ * SEQ + row0) * DMODEL + h_ * HDIM;
    float* ob1 = out + ((size_t)b_ * SEQ + row1) * DMODEL + h_ * HDIM;
    #pragma unroll
    for (int j = 0; j < 8; j++) {
        if (row0 < SEQ) *(float2*)&ob0[j * 8 + c2] = make_float2(oc[j][0] * inv0, oc[j][1] * inv0);
        if (row1 < SEQ) *(float2*)&ob1[j * 8 + c2] = make_float2(oc[j][2] * inv1, oc[j][3] * inv1);
    }
}

// ---------------------------------------------------------------------------
// K5: p = e * rowinv, in place. Pure streaming.
// ---------------------------------------------------------------------------
__global__ __launch_bounds__(256) void scale_kernel(float* __restrict__ Pext, int use_ext)
{
    float* P = use_ext ? Pext : g_scores_fallback;
    unsigned i = (blockIdx.x * 256u + threadIdx.x) * 4u;
    float inv = g_rowinv[i / SEQ];
    float4 v = *(float4*)&P[i];
    v.x *= inv; v.y *= inv; v.z *= inv; v.w *= inv;
    *(float4*)&P[i] = v;
}

// ---------------------------------------------------------------------------
extern "C" void kernel_launch(void* const* d_in, const int* in_sizes, int n_in,
                              void* d_out, int out_size)
{
    const float* x  = (const float*)d_in[0];
    const float* wq = (const float*)d_in[1];
    const float* bq = (const float*)d_in[2];
    const float* wk = (const float*)d_in[3];
    const float* bk = (const float*)d_in[4];
    const float* wv = (const float*)d_in[5];
    const float* bv = (const float*)d_in[6];
    float* out = (float*)d_out;

    int use_ext = ((size_t)out_size >= OUT_ELEMS + PATT_ELEMS) ? 1 : 0;
    float* Pext = out + OUT_ELEMS;

    {   // K1: QKV -> bf16 hi/lo (V transposed)
        dim3 grid(DMODEL / 128, (BATCH * SEQ) / 128, 3);
        qkv_kernel<<<grid, 256>>>(x, wq, bq, wk, bk, wv, bv);
    }
    {   // K2 fused: HMMA attention -> raw e + out + rowinv
        dim3 grid((SEQ + 127) / 128, BH);
        attn_kernel<<<grid, 256>>>(Pext, use_ext, out);
    }
    {   // K5: normalize p in place
        scale_kernel<<<(unsigned)(PATT_ELEMS / 4 / 256), 256>>>(Pext, use_ext);
    }
}

// round 5
// speedup vs baseline: 1.2807x; 1.0665x over previous
#include <cuda_runtime.h>
#include <cuda_bf16.h>
#include <math.h>
#include <stdint.h>

#define BATCH 8
#define SEQ 1600
#define IN_DIM 256
#define DMODEL 512
#define NHEAD 8
#define HDIM 64
#define NJOINT 25
#define BH (BATCH*NHEAD)                 // 64
#define OUT_ELEMS (BATCH*SEQ*DMODEL)     // 6,553,600
#define PATT_ELEMS ((size_t)BH*SEQ*SEQ)  // 163,840,000

// scratch (__device__ globals; no allocation allowed)
__device__ __nv_bfloat16 g_qhi[BH*SEQ*HDIM];
__device__ __nv_bfloat16 g_qlo[BH*SEQ*HDIM];
__device__ __nv_bfloat16 g_khi[BH*SEQ*HDIM];
__device__ __nv_bfloat16 g_klo[BH*SEQ*HDIM];
__device__ __nv_bfloat16 g_vthi[BH*HDIM*SEQ];   // transposed: [bh][d][s]
__device__ float g_scores_fallback[PATT_ELEMS];

#define SW(o) ((o) ^ (((o) >> 3) & 0x70))

__device__ __forceinline__ uint32_t smem_u32(const void* p) {
    uint32_t a;
    asm("{ .reg .u64 t; cvta.to.shared.u64 t, %1; cvt.u32.u64 %0, t; }" : "=r"(a) : "l"(p));
    return a;
}
__device__ __forceinline__ void ldsm4(uint32_t* r, uint32_t addr) {
    asm volatile("ldmatrix.sync.aligned.m8n8.x4.shared.b16 {%0,%1,%2,%3}, [%4];"
                 : "=r"(r[0]), "=r"(r[1]), "=r"(r[2]), "=r"(r[3]) : "r"(addr));
}
__device__ __forceinline__ void mma16816(float* c, const uint32_t* a, const uint32_t* b) {
    asm volatile("mma.sync.aligned.m16n8k16.row.col.f32.bf16.bf16.f32 "
                 "{%0,%1,%2,%3}, {%4,%5,%6,%7}, {%8,%9}, {%0,%1,%2,%3};"
                 : "+f"(c[0]), "+f"(c[1]), "+f"(c[2]), "+f"(c[3])
                 : "r"(a[0]), "r"(a[1]), "r"(a[2]), "r"(a[3]), "r"(b[0]), "r"(b[1]));
}

// ---------------------------------------------------------------------------
// K1: QKV projection (fp32 SIMT GEMM 128x128 tile). Epilogue emits bf16:
//   Q,K -> hi/lo [bh, s, d];  V(+ReLU) -> hi only, transposed [bh, d, s].
// ---------------------------------------------------------------------------
__global__ __launch_bounds__(256, 2) void qkv_kernel(
    const float* __restrict__ x,
    const float* __restrict__ wq, const float* __restrict__ bq,
    const float* __restrict__ wk, const float* __restrict__ bk,
    const float* __restrict__ wv, const float* __restrict__ bv)
{
    const float* W; const float* bias; int z = blockIdx.z;
    if (z == 0)      { W = wq; bias = bq; }
    else if (z == 1) { W = wk; bias = bk; }
    else             { W = wv; bias = bv; }

    __shared__ float xsT[32][132];
    __shared__ float ws[32][132];

    const int t  = threadIdx.x;
    const int tx = t & 15, ty = t >> 4;
    const int rowBase = blockIdx.y * 128;
    const int nBase   = blockIdx.x * 128;

    float acc[8][8] = {};

    for (int k0 = 0; k0 < IN_DIM; k0 += 32) {
        float4 av[4], bv4[4];
        #pragma unroll
        for (int p = 0; p < 4; p++) {
            int idx = t + p * 256;
            int r   = idx >> 3;
            int cg  = (idx & 7) * 4;
            av[p] = *(const float4*)&x[(size_t)(rowBase + r) * IN_DIM + k0 + cg];
            int kk = idx >> 5;
            int c  = (idx & 31) * 4;
            bv4[p] = *(const float4*)&W[(size_t)(k0 + kk) * DMODEL + nBase + c];
        }
        __syncthreads();
        #pragma unroll
        for (int p = 0; p < 4; p++) {
            int idx = t + p * 256;
            int r   = idx >> 3;
            int cg  = (idx & 7) * 4;
            xsT[cg + 0][r] = av[p].x; xsT[cg + 1][r] = av[p].y;
            xsT[cg + 2][r] = av[p].z; xsT[cg + 3][r] = av[p].w;
            int kk = idx >> 5;
            int c  = (idx & 31) * 4;
            *(float4*)&ws[kk][c] = bv4[p];
        }
        __syncthreads();
        #pragma unroll
        for (int kk = 0; kk < 32; kk++) {
            float4 A0 = *(float4*)&xsT[kk][ty * 8];
            float4 A1 = *(float4*)&xsT[kk][ty * 8 + 4];
            float4 B0 = *(float4*)&ws[kk][tx * 8];
            float4 B1 = *(float4*)&ws[kk][tx * 8 + 4];
            float ar[8] = {A0.x,A0.y,A0.z,A0.w,A1.x,A1.y,A1.z,A1.w};
            float br[8] = {B0.x,B0.y,B0.z,B0.w,B1.x,B1.y,B1.z,B1.w};
            #pragma unroll
            for (int i = 0; i < 8; i++)
                #pragma unroll
                for (int j = 0; j < 8; j++)
                    acc[i][j] += ar[i] * br[j];
        }
    }

    float bb[8];
    #pragma unroll
    for (int j = 0; j < 8; j++) bb[j] = bias[nBase + tx * 8 + j];
    const int h  = (nBase + tx * 8) >> 6;
    const int ch = (nBase + tx * 8) & 63;

    if (z < 2) {
        __nv_bfloat16* DH = (z == 0) ? g_qhi : g_khi;
        __nv_bfloat16* DL = (z == 0) ? g_qlo : g_klo;
        #pragma unroll
        for (int i = 0; i < 8; i++) {
            int r  = rowBase + ty * 8 + i;
            int b_ = r / SEQ, s_ = r % SEQ;
            __align__(16) __nv_bfloat16 hb[8], lb[8];
            #pragma unroll
            for (int j = 0; j < 8; j++) {
                float v = acc[i][j] + bb[j];
                hb[j] = __float2bfloat16(v);
                lb[j] = __float2bfloat16(v - __bfloat162float(hb[j]));
            }
            size_t base = ((size_t)(b_ * NHEAD + h) * SEQ + s_) * HDIM + ch;
            *(uint4*)&DH[base] = *(uint4*)hb;
            *(uint4*)&DL[base] = *(uint4*)lb;
        }
    } else {
        int r0 = rowBase + ty * 8;
        int b_ = r0 / SEQ, s0 = r0 % SEQ;   // 8-row group never splits a batch
        #pragma unroll
        for (int j = 0; j < 8; j++) {
            __align__(16) __nv_bfloat16 hb[8];
            #pragma unroll
            for (int i = 0; i < 8; i++)
                hb[i] = __float2bfloat16(fmaxf(acc[i][j] + bb[j], 0.f));  // ReLU
            size_t base = ((size_t)(b_ * NHEAD + h) * HDIM + (ch + j)) * SEQ + s0;
            *(uint4*)&g_vthi[base] = *(uint4*)hb;
        }
    }
}

// ---------------------------------------------------------------------------
// K2 fused: HMMA attention, two-phase (rowsum then normalized write + PV).
// Block = (bh, 128 q rows), 256 threads = 8 warps; warp w owns q rows
// [qBase+16w, +16).
//  Phase A (25 key tiles): S = QK^T (3 split-bf16 terms) -> mask+exp -> rowsum.
//  Phase B (25 key tiles): recompute S identically -> p = e/rowsum -> write p
//          (fp32, final) -> pack p to bf16 A-frags -> O += p V^T (1 term).
// Epilogue: write O (already normalized). No extra passes over p.
// ---------------------------------------------------------------------------
__global__ __launch_bounds__(256) void attn_kernel(
    float* __restrict__ Pext, int use_ext, float* __restrict__ out)
{
    __shared__ __align__(16) __nv_bfloat16 skh[64*64];
    __shared__ __align__(16) __nv_bfloat16 skl[64*64];
    __shared__ __align__(16) __nv_bfloat16 svh[64*64];

    float* P = use_ext ? Pext : g_scores_fallback;
    const int tid = threadIdx.x, w = tid >> 5, lane = tid & 31;
    const int bh = blockIdx.y;
    const int qBase = blockIdx.x * 128;

    const int row0 = qBase + w * 16 + (lane >> 2);
    const int row1 = row0 + 8;
    const int c2   = (lane & 3) * 2;
    const int fq0 = row0 / NJOINT, fq1 = row1 / NJOINT;

    const __nv_bfloat16* qh = g_qhi + (size_t)bh * SEQ * HDIM;
    const __nv_bfloat16* ql = g_qlo + (size_t)bh * SEQ * HDIM;
    const __nv_bfloat16* kh = g_khi + (size_t)bh * SEQ * HDIM;
    const __nv_bfloat16* kl = g_klo + (size_t)bh * SEQ * HDIM;
    const __nv_bfloat16* vh = g_vthi + (size_t)bh * HDIM * SEQ;

    // Q A-fragments, resident all kernel (hi & lo). qfh[t] covers d=[16t,16t+16)
    uint32_t qfh[4][4], qfl[4][4];
    {
        int r0c = min(row0, SEQ - 1), r1c = min(row1, SEQ - 1);
        #pragma unroll
        for (int t = 0; t < 4; t++) {
            qfh[t][0] = *(const uint32_t*)&qh[(size_t)r0c * HDIM + t*16 + c2];
            qfh[t][1] = *(const uint32_t*)&qh[(size_t)r1c * HDIM + t*16 + c2];
            qfh[t][2] = *(const uint32_t*)&qh[(size_t)r0c * HDIM + t*16 + 8 + c2];
            qfh[t][3] = *(const uint32_t*)&qh[(size_t)r1c * HDIM + t*16 + 8 + c2];
            qfl[t][0] = *(const uint32_t*)&ql[(size_t)r0c * HDIM + t*16 + c2];
            qfl[t][1] = *(const uint32_t*)&ql[(size_t)r1c * HDIM + t*16 + c2];
            qfl[t][2] = *(const uint32_t*)&ql[(size_t)r0c * HDIM + t*16 + 8 + c2];
            qfl[t][3] = *(const uint32_t*)&ql[(size_t)r1c * HDIM + t*16 + 8 + c2];
        }
    }

    const uint32_t skh_b = smem_u32(skh), skl_b = smem_u32(skl);
    const uint32_t svh_b = smem_u32(svh);

    const int lrow = lane & 7;
    const int lcb  = (lane >> 3) * 16;

    float rsum0 = 0.f, rsum1 = 0.f;

    // ================= Phase A: rowsum only =================
    for (int kt = 0; kt < 25; kt++) {
        const int k0 = kt * 64;
        __syncthreads();
        for (int i = tid; i < 1024; i += 256) {
            int buf = i >> 9, rem = i & 511;
            int r = rem >> 3, cb = (rem & 7) * 16;
            uint4 v = (buf == 0)
                ? *(const uint4*)((const char*)&kh[(size_t)(k0 + r) * HDIM] + cb)
                : *(const uint4*)((const char*)&kl[(size_t)(k0 + r) * HDIM] + cb);
            char* dst = (buf == 0) ? (char*)skh : (char*)skl;
            *(uint4*)(dst + SW(r * 128 + cb)) = v;
        }
        __syncthreads();

        float sc[8][4];
        #pragma unroll
        for (int jp = 0; jp < 4; jp++) {
            const int j0 = jp * 2, j1 = jp * 2 + 1;
            uint32_t b0h[8], b0l[8], b1h[8], b1l[8];
            {
                uint32_t a = SW((j0 * 8 + lrow) * 128 + lcb);
                ldsm4(b0h, skh_b + a); ldsm4(b0h + 4, skh_b + (a ^ 64));
                ldsm4(b0l, skl_b + a); ldsm4(b0l + 4, skl_b + (a ^ 64));
                uint32_t b = SW((j1 * 8 + lrow) * 128 + lcb);
                ldsm4(b1h, skh_b + b); ldsm4(b1h + 4, skh_b + (b ^ 64));
                ldsm4(b1l, skl_b + b); ldsm4(b1l + 4, skl_b + (b ^ 64));
            }
            float c0[4] = {0.f,0.f,0.f,0.f}, c1[4] = {0.f,0.f,0.f,0.f};
            #pragma unroll
            for (int t = 0; t < 4; t++) {
                mma16816(c0, qfh[t], b0h + 2*t);
                mma16816(c1, qfh[t], b1h + 2*t);
                mma16816(c0, qfh[t], b0l + 2*t);
                mma16816(c1, qfh[t], b1l + 2*t);
                mma16816(c0, qfl[t], b0h + 2*t);
                mma16816(c1, qfl[t], b1h + 2*t);
            }
            #pragma unroll
            for (int u = 0; u < 4; u++) { sc[j0][u] = c0[u]; sc[j1][u] = c1[u]; }
        }

        #pragma unroll
        for (int j = 0; j < 8; j++) {
            int kcol = k0 + j * 8 + c2;
            int fk0 = kcol / NJOINT, fk1 = (kcol + 1) / NJOINT;
            bool a00 = (fq0 != fk0) || (row0 == kcol);
            bool a01 = (fq0 != fk1) || (row0 == kcol + 1);
            bool a10 = (fq1 != fk0) || (row1 == kcol);
            bool a11 = (fq1 != fk1) || (row1 == kcol + 1);
            rsum0 += (a00 ? __expf(sc[j][0] * 0.125f) : 0.f)
                   + (a01 ? __expf(sc[j][1] * 0.125f) : 0.f);
            rsum1 += (a10 ? __expf(sc[j][2] * 0.125f) : 0.f)
                   + (a11 ? __expf(sc[j][3] * 0.125f) : 0.f);
        }
    }

    #pragma unroll
    for (int off = 1; off < 4; off <<= 1) {
        rsum0 += __shfl_xor_sync(0xffffffffu, rsum0, off);
        rsum1 += __shfl_xor_sync(0xffffffffu, rsum1, off);
    }
    const float inv0 = (row0 < SEQ) ? 1.f / rsum0 : 0.f;
    const float inv1 = (row1 < SEQ) ? 1.f / rsum1 : 0.f;

    float* prow0 = P + ((size_t)bh * SEQ + row0) * SEQ;   // deref only if row<SEQ
    float* prow1 = P + ((size_t)bh * SEQ + row1) * SEQ;

    float oc[8][4];
    #pragma unroll
    for (int j = 0; j < 8; j++) { oc[j][0]=0.f; oc[j][1]=0.f; oc[j][2]=0.f; oc[j][3]=0.f; }

    // ================= Phase B: recompute, write p, O += pV =================
    for (int kt = 0; kt < 25; kt++) {
        const int k0 = kt * 64;
        __syncthreads();
        for (int i = tid; i < 1536; i += 256) {
            int buf = i >> 9, rem = i & 511;
            int r = rem >> 3, cb = (rem & 7) * 16;
            uint4 v;
            if (buf == 0)      v = *(const uint4*)((const char*)&kh[(size_t)(k0 + r) * HDIM] + cb);
            else if (buf == 1) v = *(const uint4*)((const char*)&kl[(size_t)(k0 + r) * HDIM] + cb);
            else               v = *(const uint4*)((const char*)&vh[(size_t)r * SEQ + k0] + cb);
            char* dst = (buf == 0) ? (char*)skh : (buf == 1) ? (char*)skl : (char*)svh;
            *(uint4*)(dst + SW(r * 128 + cb)) = v;
        }
        __syncthreads();

        float sc[8][4];
        #pragma unroll
        for (int jp = 0; jp < 4; jp++) {
            const int j0 = jp * 2, j1 = jp * 2 + 1;
            uint32_t b0h[8], b0l[8], b1h[8], b1l[8];
            {
                uint32_t a = SW((j0 * 8 + lrow) * 128 + lcb);
                ldsm4(b0h, skh_b + a); ldsm4(b0h + 4, skh_b + (a ^ 64));
                ldsm4(b0l, skl_b + a); ldsm4(b0l + 4, skl_b + (a ^ 64));
                uint32_t b = SW((j1 * 8 + lrow) * 128 + lcb);
                ldsm4(b1h, skh_b + b); ldsm4(b1h + 4, skh_b + (b ^ 64));
                ldsm4(b1l, skl_b + b); ldsm4(b1l + 4, skl_b + (b ^ 64));
            }
            float c0[4] = {0.f,0.f,0.f,0.f}, c1[4] = {0.f,0.f,0.f,0.f};
            #pragma unroll
            for (int t = 0; t < 4; t++) {
                mma16816(c0, qfh[t], b0h + 2*t);
                mma16816(c1, qfh[t], b1h + 2*t);
                mma16816(c0, qfh[t], b0l + 2*t);
                mma16816(c1, qfh[t], b1l + 2*t);
                mma16816(c0, qfl[t], b0h + 2*t);
                mma16816(c1, qfl[t], b1h + 2*t);
            }
            #pragma unroll
            for (int u = 0; u < 4; u++) { sc[j0][u] = c0[u]; sc[j1][u] = c1[u]; }
        }

        uint32_t pah[4][4];
        #pragma unroll
        for (int j = 0; j < 8; j++) {
            int kcol = k0 + j * 8 + c2;
            int fk0 = kcol / NJOINT, fk1 = (kcol + 1) / NJOINT;
            bool a00 = (fq0 != fk0) || (row0 == kcol);
            bool a01 = (fq0 != fk1) || (row0 == kcol + 1);
            bool a10 = (fq1 != fk0) || (row1 == kcol);
            bool a11 = (fq1 != fk1) || (row1 == kcol + 1);
            float p00 = a00 ? __expf(sc[j][0] * 0.125f) * inv0 : 0.f;
            float p01 = a01 ? __expf(sc[j][1] * 0.125f) * inv0 : 0.f;
            float p10 = a10 ? __expf(sc[j][2] * 0.125f) * inv1 : 0.f;
            float p11 = a11 ? __expf(sc[j][3] * 0.125f) * inv1 : 0.f;
            if (row0 < SEQ) *(float2*)&prow0[kcol] = make_float2(p00, p01);
            if (row1 < SEQ) *(float2*)&prow1[kcol] = make_float2(p10, p11);
            __nv_bfloat162 h0 = __floats2bfloat162_rn(p00, p01);
            __nv_bfloat162 h1 = __floats2bfloat162_rn(p10, p11);
            int t = j >> 1, odd = (j & 1) * 2;
            pah[t][odd + 0] = *(uint32_t*)&h0;
            pah[t][odd + 1] = *(uint32_t*)&h1;
        }

        #pragma unroll
        for (int jp = 0; jp < 4; jp++) {
            const int j0 = jp * 2, j1 = jp * 2 + 1;
            uint32_t b0[8], b1[8];
            {
                uint32_t a = SW((j0 * 8 + lrow) * 128 + lcb);
                ldsm4(b0, svh_b + a); ldsm4(b0 + 4, svh_b + (a ^ 64));
                uint32_t b = SW((j1 * 8 + lrow) * 128 + lcb);
                ldsm4(b1, svh_b + b); ldsm4(b1 + 4, svh_b + (b ^ 64));
            }
            #pragma unroll
            for (int t = 0; t < 4; t++) {
                mma16816(oc[j0], pah[t], b0 + 2*t);
                mma16816(oc[j1], pah[t], b1 + 2*t);
            }
        }
    }

    const int b_ = bh >> 3, h_ = bh & 7;
    float* ob0 = out + ((size_t)b_ * SEQ + row0) * DMODEL + h_ * HDIM;
    float* ob1 = out + ((size_t)b_ * SEQ + row1) * DMODEL + h_ * HDIM;
    #pragma unroll
    for (int j = 0; j < 8; j++) {
        if (row0 < SEQ) *(float2*)&ob0[j * 8 + c2] = make_float2(oc[j][0], oc[j][1]);
        if (row1 < SEQ) *(float2*)&ob1[j * 8 + c2] = make_float2(oc[j][2], oc[j][3]);
    }
}

// ---------------------------------------------------------------------------
extern "C" void kernel_launch(void* const* d_in, const int* in_sizes, int n_in,
                              void* d_out, int out_size)
{
    const float* x  = (const float*)d_in[0];
    const float* wq = (const float*)d_in[1];
    const float* bq = (const float*)d_in[2];
    const float* wk = (const float*)d_in[3];
    const float* bk = (const float*)d_in[4];
    const float* wv = (const float*)d_in[5];
    const float* bv = (const float*)d_in[6];
    float* out = (float*)d_out;

    int use_ext = ((size_t)out_size >= OUT_ELEMS + PATT_ELEMS) ? 1 : 0;
    float* Pext = out + OUT_ELEMS;

    {   // K1: QKV -> bf16 (Q,K hi/lo; V hi transposed)
        dim3 grid(DMODEL / 128, (BATCH * SEQ) / 128, 3);
        qkv_kernel<<<grid, 256>>>(x, wq, bq, wk, bk, wv, bv);
    }
    {   // K2 fused: two-phase HMMA attention -> p (final) + out
        dim3 grid((SEQ + 127) / 128, BH);
        attn_kernel<<<grid, 256>>>(Pext, use_ext, out);
    }
}

// round 6
// speedup vs baseline: 3.0592x; 2.3887x over previous
#include <cuda_runtime.h>
#include <cuda_fp16.h>
#include <math.h>
#include <stdint.h>

#define BATCH 8
#define SEQ 1600
#define IN_DIM 256
#define DMODEL 512
#define NHEAD 8
#define HDIM 64
#define NJOINT 25
#define BH (BATCH*NHEAD)                 // 64
#define OUT_ELEMS (BATCH*SEQ*DMODEL)     // 6,553,600
#define PATT_ELEMS ((size_t)BH*SEQ*SEQ)  // 163,840,000

// scratch (__device__ globals; no allocation allowed)
__device__ __half g_q16[BH*SEQ*HDIM];
__device__ __half g_k16[BH*SEQ*HDIM];
__device__ __half g_vt16[BH*HDIM*SEQ];   // transposed: [bh][d][s]
__device__ float g_scores_fallback[PATT_ELEMS];

#define SW(o) ((o) ^ (((o) >> 3) & 0x70))

__device__ __forceinline__ uint32_t smem_u32(const void* p) {
    uint32_t a;
    asm("{ .reg .u64 t; cvta.to.shared.u64 t, %1; cvt.u32.u64 %0, t; }" : "=r"(a) : "l"(p));
    return a;
}
__device__ __forceinline__ void ldsm4(uint32_t* r, uint32_t addr) {
    asm volatile("ldmatrix.sync.aligned.m8n8.x4.shared.b16 {%0,%1,%2,%3}, [%4];"
                 : "=r"(r[0]), "=r"(r[1]), "=r"(r[2]), "=r"(r[3]) : "r"(addr));
}
__device__ __forceinline__ void mma16816(float* c, const uint32_t* a, const uint32_t* b) {
    asm volatile("mma.sync.aligned.m16n8k16.row.col.f32.f16.f16.f32 "
                 "{%0,%1,%2,%3}, {%4,%5,%6,%7}, {%8,%9}, {%0,%1,%2,%3};"
                 : "+f"(c[0]), "+f"(c[1]), "+f"(c[2]), "+f"(c[3])
                 : "r"(a[0]), "r"(a[1]), "r"(a[2]), "r"(a[3]), "r"(b[0]), "r"(b[1]));
}

// ---------------------------------------------------------------------------
// K1: QKV projection (fp32 SIMT GEMM 128x128 tile). Epilogue emits fp16:
//   Q,K -> [bh, s, d];  V(+ReLU) -> transposed [bh, d, s].
// ---------------------------------------------------------------------------
__global__ __launch_bounds__(256, 2) void qkv_kernel(
    const float* __restrict__ x,
    const float* __restrict__ wq, const float* __restrict__ bq,
    const float* __restrict__ wk, const float* __restrict__ bk,
    const float* __restrict__ wv, const float* __restrict__ bv)
{
    const float* W; const float* bias; int z = blockIdx.z;
    if (z == 0)      { W = wq; bias = bq; }
    else if (z == 1) { W = wk; bias = bk; }
    else             { W = wv; bias = bv; }

    __shared__ float xsT[32][132];
    __shared__ float ws[32][132];

    const int t  = threadIdx.x;
    const int tx = t & 15, ty = t >> 4;
    const int rowBase = blockIdx.y * 128;
    const int nBase   = blockIdx.x * 128;

    float acc[8][8] = {};

    for (int k0 = 0; k0 < IN_DIM; k0 += 32) {
        float4 av[4], bv4[4];
        #pragma unroll
        for (int p = 0; p < 4; p++) {
            int idx = t + p * 256;
            int r   = idx >> 3;
            int cg  = (idx & 7) * 4;
            av[p] = *(const float4*)&x[(size_t)(rowBase + r) * IN_DIM + k0 + cg];
            int kk = idx >> 5;
            int c  = (idx & 31) * 4;
            bv4[p] = *(const float4*)&W[(size_t)(k0 + kk) * DMODEL + nBase + c];
        }
        __syncthreads();
        #pragma unroll
        for (int p = 0; p < 4; p++) {
            int idx = t + p * 256;
            int r   = idx >> 3;
            int cg  = (idx & 7) * 4;
            xsT[cg + 0][r] = av[p].x; xsT[cg + 1][r] = av[p].y;
            xsT[cg + 2][r] = av[p].z; xsT[cg + 3][r] = av[p].w;
            int kk = idx >> 5;
            int c  = (idx & 31) * 4;
            *(float4*)&ws[kk][c] = bv4[p];
        }
        __syncthreads();
        #pragma unroll
        for (int kk = 0; kk < 32; kk++) {
            float4 A0 = *(float4*)&xsT[kk][ty * 8];
            float4 A1 = *(float4*)&xsT[kk][ty * 8 + 4];
            float4 B0 = *(float4*)&ws[kk][tx * 8];
            float4 B1 = *(float4*)&ws[kk][tx * 8 + 4];
            float ar[8] = {A0.x,A0.y,A0.z,A0.w,A1.x,A1.y,A1.z,A1.w};
            float br[8] = {B0.x,B0.y,B0.z,B0.w,B1.x,B1.y,B1.z,B1.w};
            #pragma unroll
            for (int i = 0; i < 8; i++)
                #pragma unroll
                for (int j = 0; j < 8; j++)
                    acc[i][j] += ar[i] * br[j];
        }
    }

    float bb[8];
    #pragma unroll
    for (int j = 0; j < 8; j++) bb[j] = bias[nBase + tx * 8 + j];
    const int h  = (nBase + tx * 8) >> 6;
    const int ch = (nBase + tx * 8) & 63;

    if (z < 2) {
        __half* D = (z == 0) ? g_q16 : g_k16;
        #pragma unroll
        for (int i = 0; i < 8; i++) {
            int r  = rowBase + ty * 8 + i;
            int b_ = r / SEQ, s_ = r % SEQ;
            __align__(16) __half hb[8];
            #pragma unroll
            for (int j = 0; j < 8; j++)
                hb[j] = __float2half_rn(acc[i][j] + bb[j]);
            size_t base = ((size_t)(b_ * NHEAD + h) * SEQ + s_) * HDIM + ch;
            *(uint4*)&D[base] = *(uint4*)hb;
        }
    } else {
        int r0 = rowBase + ty * 8;
        int b_ = r0 / SEQ, s0 = r0 % SEQ;   // 8-row group never splits a batch
        #pragma unroll
        for (int j = 0; j < 8; j++) {
            __align__(16) __half hb[8];
            #pragma unroll
            for (int i = 0; i < 8; i++)
                hb[i] = __float2half_rn(fmaxf(acc[i][j] + bb[j], 0.f));  // ReLU
            size_t base = ((size_t)(b_ * NHEAD + h) * HDIM + (ch + j)) * SEQ + s0;
            *(uint4*)&g_vt16[base] = *(uint4*)hb;
        }
    }
}

// ---------------------------------------------------------------------------
// K2 fused: fp16 HMMA attention, two-phase.
// Block = (bh, 128 q rows), 256 threads = 8 warps; warp w owns q rows
// [qBase+16w, +16).
//  Phase A (25 key tiles of 64): S = QK^T (1 fp16 term) -> mask+exp -> rowsum.
//  Phase B: recompute S -> p = e*inv -> write p (fp32, final) -> fp16 A-frags
//           -> O += p V^T.
// ---------------------------------------------------------------------------
__global__ __launch_bounds__(256, 2) void attn_kernel(
    float* __restrict__ Pext, int use_ext, float* __restrict__ out)
{
    __shared__ __align__(16) __half sk[64*64];
    __shared__ __align__(16) __half sv[64*64];

    float* P = use_ext ? Pext : g_scores_fallback;
    const int tid = threadIdx.x, w = tid >> 5, lane = tid & 31;
    const int bh = blockIdx.y;
    const int qBase = blockIdx.x * 128;

    const int row0 = qBase + w * 16 + (lane >> 2);
    const int row1 = row0 + 8;
    const int c2   = (lane & 3) * 2;
    const int fq0 = row0 / NJOINT, fq1 = row1 / NJOINT;

    const __half* q = g_q16 + (size_t)bh * SEQ * HDIM;
    const __half* k = g_k16 + (size_t)bh * SEQ * HDIM;
    const __half* v = g_vt16 + (size_t)bh * HDIM * SEQ;

    // Q A-fragments resident all kernel: qf[t] covers d=[16t,16t+16)
    uint32_t qf[4][4];
    {
        int r0c = min(row0, SEQ - 1), r1c = min(row1, SEQ - 1);
        #pragma unroll
        for (int t = 0; t < 4; t++) {
            qf[t][0] = *(const uint32_t*)&q[(size_t)r0c * HDIM + t*16 + c2];
            qf[t][1] = *(const uint32_t*)&q[(size_t)r1c * HDIM + t*16 + c2];
            qf[t][2] = *(const uint32_t*)&q[(size_t)r0c * HDIM + t*16 + 8 + c2];
            qf[t][3] = *(const uint32_t*)&q[(size_t)r1c * HDIM + t*16 + 8 + c2];
        }
    }

    const uint32_t sk_b = smem_u32(sk), sv_b = smem_u32(sv);
    const int lrow = lane & 7;
    const int lcb  = (lane >> 3) * 16;

    float rsum0 = 0.f, rsum1 = 0.f;

    // ================= Phase A: rowsum only =================
    for (int kt = 0; kt < 25; kt++) {
        const int k0 = kt * 64;
        __syncthreads();
        #pragma unroll
        for (int p = 0; p < 2; p++) {
            int i = tid + p * 256;
            int r = i >> 3, cb = (i & 7) * 16;
            *(uint4*)((char*)sk + SW(r * 128 + cb)) =
                *(const uint4*)((const char*)&k[(size_t)(k0 + r) * HDIM] + cb);
        }
        __syncthreads();

        #pragma unroll
        for (int jp = 0; jp < 4; jp++) {
            const int j0 = jp * 2, j1 = jp * 2 + 1;
            uint32_t b0[8], b1[8];
            {
                uint32_t a = SW((j0 * 8 + lrow) * 128 + lcb);
                ldsm4(b0, sk_b + a); ldsm4(b0 + 4, sk_b + (a ^ 64));
                uint32_t b = SW((j1 * 8 + lrow) * 128 + lcb);
                ldsm4(b1, sk_b + b); ldsm4(b1 + 4, sk_b + (b ^ 64));
            }
            float c0[4] = {0.f,0.f,0.f,0.f}, c1[4] = {0.f,0.f,0.f,0.f};
            #pragma unroll
            for (int t = 0; t < 4; t++) {
                mma16816(c0, qf[t], b0 + 2*t);
                mma16816(c1, qf[t], b1 + 2*t);
            }
            #pragma unroll
            for (int jj = 0; jj < 2; jj++) {
                const float* cc = jj ? c1 : c0;
                int kcol = k0 + (jp * 2 + jj) * 8 + c2;
                int fk0 = kcol / NJOINT, fk1 = (kcol + 1) / NJOINT;
                bool a00 = (fq0 != fk0) || (row0 == kcol);
                bool a01 = (fq0 != fk1) || (row0 == kcol + 1);
                bool a10 = (fq1 != fk0) || (row1 == kcol);
                bool a11 = (fq1 != fk1) || (row1 == kcol + 1);
                rsum0 += (a00 ? __expf(cc[0] * 0.125f) : 0.f)
                       + (a01 ? __expf(cc[1] * 0.125f) : 0.f);
                rsum1 += (a10 ? __expf(cc[2] * 0.125f) : 0.f)
                       + (a11 ? __expf(cc[3] * 0.125f) : 0.f);
            }
        }
    }

    #pragma unroll
    for (int off = 1; off < 4; off <<= 1) {
        rsum0 += __shfl_xor_sync(0xffffffffu, rsum0, off);
        rsum1 += __shfl_xor_sync(0xffffffffu, rsum1, off);
    }
    const float inv0 = (row0 < SEQ) ? 1.f / rsum0 : 0.f;
    const float inv1 = (row1 < SEQ) ? 1.f / rsum1 : 0.f;

    float* prow0 = P + ((size_t)bh * SEQ + row0) * SEQ;   // deref only if row<SEQ
    float* prow1 = P + ((size_t)bh * SEQ + row1) * SEQ;

    float oc[8][4];
    #pragma unroll
    for (int j = 0; j < 8; j++) { oc[j][0]=0.f; oc[j][1]=0.f; oc[j][2]=0.f; oc[j][3]=0.f; }

    // ================= Phase B: recompute, write p, O += pV =================
    for (int kt = 0; kt < 25; kt++) {
        const int k0 = kt * 64;
        __syncthreads();
        #pragma unroll
        for (int p = 0; p < 4; p++) {
            int i = tid + p * 256;
            int buf = i >> 9, rem = i & 511;
            int r = rem >> 3, cb = (rem & 7) * 16;
            if (buf == 0)
                *(uint4*)((char*)sk + SW(r * 128 + cb)) =
                    *(const uint4*)((const char*)&k[(size_t)(k0 + r) * HDIM] + cb);
            else
                *(uint4*)((char*)sv + SW(r * 128 + cb)) =
                    *(const uint4*)((const char*)&v[(size_t)r * SEQ + k0] + cb);
        }
        __syncthreads();

        uint32_t pa[4][4];
        #pragma unroll
        for (int jp = 0; jp < 4; jp++) {
            const int j0 = jp * 2, j1 = jp * 2 + 1;
            uint32_t b0[8], b1[8];
            {
                uint32_t a = SW((j0 * 8 + lrow) * 128 + lcb);
                ldsm4(b0, sk_b + a); ldsm4(b0 + 4, sk_b + (a ^ 64));
                uint32_t b = SW((j1 * 8 + lrow) * 128 + lcb);
                ldsm4(b1, sk_b + b); ldsm4(b1 + 4, sk_b + (b ^ 64));
            }
            float c0[4] = {0.f,0.f,0.f,0.f}, c1[4] = {0.f,0.f,0.f,0.f};
            #pragma unroll
            for (int t = 0; t < 4; t++) {
                mma16816(c0, qf[t], b0 + 2*t);
                mma16816(c1, qf[t], b1 + 2*t);
            }
            float p00, p01, p10, p11;
            #pragma unroll
            for (int jj = 0; jj < 2; jj++) {
                const float* cc = jj ? c1 : c0;
                int kcol = k0 + (jp * 2 + jj) * 8 + c2;
                int fk0 = kcol / NJOINT, fk1 = (kcol + 1) / NJOINT;
                bool a00 = (fq0 != fk0) || (row0 == kcol);
                bool a01 = (fq0 != fk1) || (row0 == kcol + 1);
                bool a10 = (fq1 != fk0) || (row1 == kcol);
                bool a11 = (fq1 != fk1) || (row1 == kcol + 1);
                p00 = a00 ? __expf(cc[0] * 0.125f) * inv0 : 0.f;
                p01 = a01 ? __expf(cc[1] * 0.125f) * inv0 : 0.f;
                p10 = a10 ? __expf(cc[2] * 0.125f) * inv1 : 0.f;
                p11 = a11 ? __expf(cc[3] * 0.125f) * inv1 : 0.f;
                if (row0 < SEQ) *(float2*)&prow0[kcol] = make_float2(p00, p01);
                if (row1 < SEQ) *(float2*)&prow1[kcol] = make_float2(p10, p11);
                __half2 h0 = __floats2half2_rn(p00, p01);
                __half2 h1 = __floats2half2_rn(p10, p11);
                pa[jp][jj * 2 + 0] = *(uint32_t*)&h0;
                pa[jp][jj * 2 + 1] = *(uint32_t*)&h1;
            }
        }

        #pragma unroll
        for (int jp = 0; jp < 4; jp++) {
            const int j0 = jp * 2, j1 = jp * 2 + 1;
            uint32_t b0[8], b1[8];
            {
                uint32_t a = SW((j0 * 8 + lrow) * 128 + lcb);
                ldsm4(b0, sv_b + a); ldsm4(b0 + 4, sv_b + (a ^ 64));
                uint32_t b = SW((j1 * 8 + lrow) * 128 + lcb);
                ldsm4(b1, sv_b + b); ldsm4(b1 + 4, sv_b + (b ^ 64));
            }
            #pragma unroll
            for (int t = 0; t < 4; t++) {
                mma16816(oc[j0], pa[t], b0 + 2*t);
                mma16816(oc[j1], pa[t], b1 + 2*t);
            }
        }
    }

    const int b_ = bh >> 3, h_ = bh & 7;
    float* ob0 = out + ((size_t)b_ * SEQ + row0) * DMODEL + h_ * HDIM;
    float* ob1 = out + ((size_t)b_ * SEQ + row1) * DMODEL + h_ * HDIM;
    #pragma unroll
    for (int j = 0; j < 8; j++) {
        if (row0 < SEQ) *(float2*)&ob0[j * 8 + c2] = make_float2(oc[j][0], oc[j][1]);
        if (row1 < SEQ) *(float2*)&ob1[j * 8 + c2] = make_float2(oc[j][2], oc[j][3]);
    }
}

// ---------------------------------------------------------------------------
extern "C" void kernel_launch(void* const* d_in, const int* in_sizes, int n_in,
                              void* d_out, int out_size)
{
    const float* x  = (const float*)d_in[0];
    const float* wq = (const float*)d_in[1];
    const float* bq = (const float*)d_in[2];
    const float* wk = (const float*)d_in[3];
    const float* bk = (const float*)d_in[4];
    const float* wv = (const float*)d_in[5];
    const float* bv = (const float*)d_in[6];
    float* out = (float*)d_out;

    int use_ext = ((size_t)out_size >= OUT_ELEMS + PATT_ELEMS) ? 1 : 0;
    float* Pext = out + OUT_ELEMS;

    {   // K1: QKV -> fp16 (V transposed)
        dim3 grid(DMODEL / 128, (BATCH * SEQ) / 128, 3);
        qkv_kernel<<<grid, 256>>>(x, wq, bq, wk, bk, wv, bv);
    }
    {   // K2 fused: two-phase fp16 HMMA attention -> p (final) + out
        dim3 grid((SEQ + 127) / 128, BH);
        attn_kernel<<<grid, 256>>>(Pext, use_ext, out);
    }
}

// round 7
// speedup vs baseline: 3.3407x; 1.0920x over previous
#include <cuda_runtime.h>
#include <cuda_fp16.h>
#include <math.h>
#include <stdint.h>

#define BATCH 8
#define SEQ 1600
#define IN_DIM 256
#define DMODEL 512
#define NHEAD 8
#define HDIM 64
#define NJOINT 25
#define BH (BATCH*NHEAD)                 // 64
#define OUT_ELEMS (BATCH*SEQ*DMODEL)     // 6,553,600
#define PATT_ELEMS ((size_t)BH*SEQ*SEQ)  // 163,840,000

// scratch (__device__ globals; no allocation allowed)
__device__ __half g_q16[BH*SEQ*HDIM];
__device__ __half g_k16[BH*SEQ*HDIM];
__device__ __half g_vt16[BH*HDIM*SEQ];   // transposed: [bh][d][s]
__device__ float g_scores_fallback[PATT_ELEMS];

#define SW(o) ((o) ^ (((o) >> 3) & 0x70))

__device__ __forceinline__ uint32_t smem_u32(const void* p) {
    uint32_t a;
    asm("{ .reg .u64 t; cvta.to.shared.u64 t, %1; cvt.u32.u64 %0, t; }" : "=r"(a) : "l"(p));
    return a;
}
__device__ __forceinline__ void ldsm4(uint32_t* r, uint32_t addr) {
    asm volatile("ldmatrix.sync.aligned.m8n8.x4.shared.b16 {%0,%1,%2,%3}, [%4];"
                 : "=r"(r[0]), "=r"(r[1]), "=r"(r[2]), "=r"(r[3]) : "r"(addr));
}
__device__ __forceinline__ void mma16816(float* c, const uint32_t* a, const uint32_t* b) {
    asm volatile("mma.sync.aligned.m16n8k16.row.col.f32.f16.f16.f32 "
                 "{%0,%1,%2,%3}, {%4,%5,%6,%7}, {%8,%9}, {%0,%1,%2,%3};"
                 : "+f"(c[0]), "+f"(c[1]), "+f"(c[2]), "+f"(c[3])
                 : "r"(a[0]), "r"(a[1]), "r"(a[2]), "r"(a[3]), "r"(b[0]), "r"(b[1]));
}
__device__ __forceinline__ void cpasync16(uint32_t dst, const void* src) {
    asm volatile("cp.async.cg.shared.global [%0], [%1], 16;" :: "r"(dst), "l"(src));
}
__device__ __forceinline__ void cp_commit() { asm volatile("cp.async.commit_group;"); }
__device__ __forceinline__ void cp_wait1() { asm volatile("cp.async.wait_group 1;"); }
__device__ __forceinline__ void cp_wait0() { asm volatile("cp.async.wait_group 0;"); }

// ---------------------------------------------------------------------------
// K1: QKV projection (fp32 SIMT GEMM 128x128 tile). Epilogue emits fp16:
//   Q,K -> [bh, s, d];  V(+ReLU) -> transposed [bh, d, s].
// ---------------------------------------------------------------------------
__global__ __launch_bounds__(256, 2) void qkv_kernel(
    const float* __restrict__ x,
    const float* __restrict__ wq, const float* __restrict__ bq,
    const float* __restrict__ wk, const float* __restrict__ bk,
    const float* __restrict__ wv, const float* __restrict__ bv)
{
    const float* W; const float* bias; int z = blockIdx.z;
    if (z == 0)      { W = wq; bias = bq; }
    else if (z == 1) { W = wk; bias = bk; }
    else             { W = wv; bias = bv; }

    __shared__ float xsT[32][132];
    __shared__ float ws[32][132];

    const int t  = threadIdx.x;
    const int tx = t & 15, ty = t >> 4;
    const int rowBase = blockIdx.y * 128;
    const int nBase   = blockIdx.x * 128;

    float acc[8][8] = {};

    for (int k0 = 0; k0 < IN_DIM; k0 += 32) {
        float4 av[4], bv4[4];
        #pragma unroll
        for (int p = 0; p < 4; p++) {
            int idx = t + p * 256;
            int r   = idx >> 3;
            int cg  = (idx & 7) * 4;
            av[p] = *(const float4*)&x[(size_t)(rowBase + r) * IN_DIM + k0 + cg];
            int kk = idx >> 5;
            int c  = (idx & 31) * 4;
            bv4[p] = *(const float4*)&W[(size_t)(k0 + kk) * DMODEL + nBase + c];
        }
        __syncthreads();
        #pragma unroll
        for (int p = 0; p < 4; p++) {
            int idx = t + p * 256;
            int r   = idx >> 3;
            int cg  = (idx & 7) * 4;
            xsT[cg + 0][r] = av[p].x; xsT[cg + 1][r] = av[p].y;
            xsT[cg + 2][r] = av[p].z; xsT[cg + 3][r] = av[p].w;
            int kk = idx >> 5;
            int c  = (idx & 31) * 4;
            *(float4*)&ws[kk][c] = bv4[p];
        }
        __syncthreads();
        #pragma unroll
        for (int kk = 0; kk < 32; kk++) {
            float4 A0 = *(float4*)&xsT[kk][ty * 8];
            float4 A1 = *(float4*)&xsT[kk][ty * 8 + 4];
            float4 B0 = *(float4*)&ws[kk][tx * 8];
            float4 B1 = *(float4*)&ws[kk][tx * 8 + 4];
            float ar[8] = {A0.x,A0.y,A0.z,A0.w,A1.x,A1.y,A1.z,A1.w};
            float br[8] = {B0.x,B0.y,B0.z,B0.w,B1.x,B1.y,B1.z,B1.w};
            #pragma unroll
            for (int i = 0; i < 8; i++)
                #pragma unroll
                for (int j = 0; j < 8; j++)
                    acc[i][j] += ar[i] * br[j];
        }
    }

    float bb[8];
    #pragma unroll
    for (int j = 0; j < 8; j++) bb[j] = bias[nBase + tx * 8 + j];
    const int h  = (nBase + tx * 8) >> 6;
    const int ch = (nBase + tx * 8) & 63;

    if (z < 2) {
        __half* D = (z == 0) ? g_q16 : g_k16;
        #pragma unroll
        for (int i = 0; i < 8; i++) {
            int r  = rowBase + ty * 8 + i;
            int b_ = r / SEQ, s_ = r % SEQ;
            __align__(16) __half hb[8];
            #pragma unroll
            for (int j = 0; j < 8; j++)
                hb[j] = __float2half_rn(acc[i][j] + bb[j]);
            size_t base = ((size_t)(b_ * NHEAD + h) * SEQ + s_) * HDIM + ch;
            *(uint4*)&D[base] = *(uint4*)hb;
        }
    } else {
        int r0 = rowBase + ty * 8;
        int b_ = r0 / SEQ, s0 = r0 % SEQ;   // 8-row group never splits a batch
        #pragma unroll
        for (int j = 0; j < 8; j++) {
            __align__(16) __half hb[8];
            #pragma unroll
            for (int i = 0; i < 8; i++)
                hb[i] = __float2half_rn(fmaxf(acc[i][j] + bb[j], 0.f));  // ReLU
            size_t base = ((size_t)(b_ * NHEAD + h) * HDIM + (ch + j)) * SEQ + s0;
            *(uint4*)&g_vt16[base] = *(uint4*)hb;
        }
    }
}

// ---------------------------------------------------------------------------
// K2 fused: fp16 HMMA attention, two-phase, cp.async double-buffered.
// Block = (bh, 128 q rows), 256 threads = 8 warps; warp w owns q rows
// [qBase+16w, +16). 25 key tiles of 64 (1600 = 25*64, no k tail).
//  Phase A: S = QK^T -> mask (compare-based) + exp -> rowsum.
//  Phase B: recompute S -> p = e*inv -> write p (fp32, final) -> O += p V^T.
// ---------------------------------------------------------------------------
__global__ __launch_bounds__(256, 2) void attn_kernel(
    float* __restrict__ Pext, int use_ext, float* __restrict__ out)
{
    __shared__ __align__(16) __half sk[2][64*64];
    __shared__ __align__(16) __half sv[2][64*64];

    float* P = use_ext ? Pext : g_scores_fallback;
    const int tid = threadIdx.x, w = tid >> 5, lane = tid & 31;
    const int bh = blockIdx.y;
    const int qBase = blockIdx.x * 128;

    const int row0 = qBase + w * 16 + (lane >> 2);
    const int row1 = row0 + 8;
    const int c2   = (lane & 3) * 2;
    const int lo0 = (row0 / NJOINT) * NJOINT, hi0 = lo0 + NJOINT;
    const int lo1 = (row1 / NJOINT) * NJOINT, hi1 = lo1 + NJOINT;

    const __half* q = g_q16 + (size_t)bh * SEQ * HDIM;
    const char* kB = (const char*)(g_k16 + (size_t)bh * SEQ * HDIM);
    const char* vB = (const char*)(g_vt16 + (size_t)bh * HDIM * SEQ);

    // Q A-fragments resident all kernel: qf[t] covers d=[16t,16t+16)
    uint32_t qf[4][4];
    {
        int r0c = min(row0, SEQ - 1), r1c = min(row1, SEQ - 1);
        #pragma unroll
        for (int t = 0; t < 4; t++) {
            qf[t][0] = *(const uint32_t*)&q[(size_t)r0c * HDIM + t*16 + c2];
            qf[t][1] = *(const uint32_t*)&q[(size_t)r1c * HDIM + t*16 + c2];
            qf[t][2] = *(const uint32_t*)&q[(size_t)r0c * HDIM + t*16 + 8 + c2];
            qf[t][3] = *(const uint32_t*)&q[(size_t)r1c * HDIM + t*16 + 8 + c2];
        }
    }

    const uint32_t sk_b = smem_u32(sk), sv_b = smem_u32(sv);

    // hoisted per-thread geometry
    uint32_t dstoff[2]; uint32_t srcKoff[2], srcVoff[2];
    #pragma unroll
    for (int p = 0; p < 2; p++) {
        int i = tid + p * 256;
        int r = i >> 3, cb = (i & 7) * 16;
        dstoff[p]  = SW(r * 128 + cb);
        srcKoff[p] = r * 128 + cb;          // + kt*8192
        srcVoff[p] = r * (SEQ * 2) + cb;    // + kt*128
    }
    const int lrow = lane & 7;
    const int lcb  = (lane >> 3) * 16;
    uint32_t lof[8];
    #pragma unroll
    for (int j = 0; j < 8; j++) lof[j] = SW((j * 8 + lrow) * 128 + lcb);

    float rsum0 = 0.f, rsum1 = 0.f;

    // ================= Phase A: rowsum only =================
    #pragma unroll 1
    for (int p = 0; p < 2; p++)
        cpasync16(sk_b + dstoff[p], kB + srcKoff[p]);
    cp_commit();

    #pragma unroll 1
    for (int kt = 0; kt < 25; kt++) {
        const int k0 = kt * 64;
        const uint32_t cb_ = sk_b + (kt & 1) * 8192;
        if (kt + 1 < 25) {
            const uint32_t nb = sk_b + ((kt + 1) & 1) * 8192;
            #pragma unroll
            for (int p = 0; p < 2; p++)
                cpasync16(nb + dstoff[p], kB + (kt + 1) * 8192 + srcKoff[p]);
            cp_commit();
            cp_wait1();
        } else cp_wait0();
        __syncthreads();

        #pragma unroll
        for (int jp = 0; jp < 4; jp++) {
            uint32_t b0[8], b1[8];
            {
                uint32_t a = cb_ + lof[jp * 2];
                ldsm4(b0, a); ldsm4(b0 + 4, a ^ 64);
                uint32_t b = cb_ + lof[jp * 2 + 1];
                ldsm4(b1, b); ldsm4(b1 + 4, b ^ 64);
            }
            float c0[4] = {0.f,0.f,0.f,0.f}, c1[4] = {0.f,0.f,0.f,0.f};
            #pragma unroll
            for (int t = 0; t < 4; t++) {
                mma16816(c0, qf[t], b0 + 2*t);
                mma16816(c1, qf[t], b1 + 2*t);
            }
            #pragma unroll
            for (int jj = 0; jj < 2; jj++) {
                const float* cc = jj ? c1 : c0;
                int ka = k0 + (jp * 2 + jj) * 8 + c2, kb2 = ka + 1;
                bool a00 = (ka  < lo0) | (ka  >= hi0) | (ka  == row0);
                bool a01 = (kb2 < lo0) | (kb2 >= hi0) | (kb2 == row0);
                bool a10 = (ka  < lo1) | (ka  >= hi1) | (ka  == row1);
                bool a11 = (kb2 < lo1) | (kb2 >= hi1) | (kb2 == row1);
                rsum0 += (a00 ? __expf(cc[0] * 0.125f) : 0.f)
                       + (a01 ? __expf(cc[1] * 0.125f) : 0.f);
                rsum1 += (a10 ? __expf(cc[2] * 0.125f) : 0.f)
                       + (a11 ? __expf(cc[3] * 0.125f) : 0.f);
            }
        }
        __syncthreads();
    }

    #pragma unroll
    for (int off = 1; off < 4; off <<= 1) {
        rsum0 += __shfl_xor_sync(0xffffffffu, rsum0, off);
        rsum1 += __shfl_xor_sync(0xffffffffu, rsum1, off);
    }
    const float inv0 = (row0 < SEQ) ? 1.f / rsum0 : 0.f;
    const float inv1 = (row1 < SEQ) ? 1.f / rsum1 : 0.f;

    float* prow0 = P + ((size_t)bh * SEQ + row0) * SEQ;   // deref only if row<SEQ
    float* prow1 = P + ((size_t)bh * SEQ + row1) * SEQ;

    float oc[8][4];
    #pragma unroll
    for (int j = 0; j < 8; j++) { oc[j][0]=0.f; oc[j][1]=0.f; oc[j][2]=0.f; oc[j][3]=0.f; }

    // ================= Phase B: recompute, write p, O += pV =================
    #pragma unroll
    for (int p = 0; p < 2; p++) {
        cpasync16(sk_b + dstoff[p], kB + srcKoff[p]);
        cpasync16(sv_b + dstoff[p], vB + srcVoff[p]);
    }
    cp_commit();

    #pragma unroll 1
    for (int kt = 0; kt < 25; kt++) {
        const int k0 = kt * 64;
        const uint32_t ckb = sk_b + (kt & 1) * 8192;
        const uint32_t cvb = sv_b + (kt & 1) * 8192;
        if (kt + 1 < 25) {
            const uint32_t off = ((kt + 1) & 1) * 8192;
            #pragma unroll
            for (int p = 0; p < 2; p++) {
                cpasync16(sk_b + off + dstoff[p], kB + (kt + 1) * 8192 + srcKoff[p]);
                cpasync16(sv_b + off + dstoff[p], vB + (kt + 1) * 128  + srcVoff[p]);
            }
            cp_commit();
            cp_wait1();
        } else cp_wait0();
        __syncthreads();

        uint32_t pa[4][4];
        #pragma unroll
        for (int jp = 0; jp < 4; jp++) {
            uint32_t b0[8], b1[8];
            {
                uint32_t a = ckb + lof[jp * 2];
                ldsm4(b0, a); ldsm4(b0 + 4, a ^ 64);
                uint32_t b = ckb + lof[jp * 2 + 1];
                ldsm4(b1, b); ldsm4(b1 + 4, b ^ 64);
            }
            float c0[4] = {0.f,0.f,0.f,0.f}, c1[4] = {0.f,0.f,0.f,0.f};
            #pragma unroll
            for (int t = 0; t < 4; t++) {
                mma16816(c0, qf[t], b0 + 2*t);
                mma16816(c1, qf[t], b1 + 2*t);
            }
            #pragma unroll
            for (int jj = 0; jj < 2; jj++) {
                const float* cc = jj ? c1 : c0;
                int ka = k0 + (jp * 2 + jj) * 8 + c2, kb2 = ka + 1;
                bool a00 = (ka  < lo0) | (ka  >= hi0) | (ka  == row0);
                bool a01 = (kb2 < lo0) | (kb2 >= hi0) | (kb2 == row0);
                bool a10 = (ka  < lo1) | (ka  >= hi1) | (ka  == row1);
                bool a11 = (kb2 < lo1) | (kb2 >= hi1) | (kb2 == row1);
                float p00 = a00 ? __expf(cc[0] * 0.125f) * inv0 : 0.f;
                float p01 = a01 ? __expf(cc[1] * 0.125f) * inv0 : 0.f;
                float p10 = a10 ? __expf(cc[2] * 0.125f) * inv1 : 0.f;
                float p11 = a11 ? __expf(cc[3] * 0.125f) * inv1 : 0.f;
                if (row0 < SEQ) *(float2*)&prow0[ka] = make_float2(p00, p01);
                if (row1 < SEQ) *(float2*)&prow1[ka] = make_float2(p10, p11);
                __half2 h0 = __floats2half2_rn(p00, p01);
                __half2 h1 = __floats2half2_rn(p10, p11);
                pa[jp][jj * 2 + 0] = *(uint32_t*)&h0;
                pa[jp][jj * 2 + 1] = *(uint32_t*)&h1;
            }
        }

        #pragma unroll
        for (int jp = 0; jp < 4; jp++) {
            uint32_t b0[8], b1[8];
            {
                uint32_t a = cvb + lof[jp * 2];
                ldsm4(b0, a); ldsm4(b0 + 4, a ^ 64);
                uint32_t b = cvb + lof[jp * 2 + 1];
                ldsm4(b1, b); ldsm4(b1 + 4, b ^ 64);
            }
            #pragma unroll
            for (int t = 0; t < 4; t++) {
                mma16816(oc[jp * 2],     pa[t], b0 + 2*t);
                mma16816(oc[jp * 2 + 1], pa[t], b1 + 2*t);
            }
        }
        __syncthreads();
    }

    const int b_ = bh >> 3, h_ = bh & 7;
    float* ob0 = out + ((size_t)b_ * SEQ + row0) * DMODEL + h_ * HDIM;
    float* ob1 = out + ((size_t)b_ * SEQ + row1) * DMODEL + h_ * HDIM;
    #pragma unroll
    for (int j = 0; j < 8; j++) {
        if (row0 < SEQ) *(float2*)&ob0[j * 8 + c2] = make_float2(oc[j][0], oc[j][1]);
        if (row1 < SEQ) *(float2*)&ob1[j * 8 + c2] = make_float2(oc[j][2], oc[j][3]);
    }
}

// ---------------------------------------------------------------------------
extern "C" void kernel_launch(void* const* d_in, const int* in_sizes, int n_in,
                              void* d_out, int out_size)
{
    const float* x  = (const float*)d_in[0];
    const float* wq = (const float*)d_in[1];
    const float* bq = (const float*)d_in[2];
    const float* wk = (const float*)d_in[3];
    const float* bk = (const float*)d_in[4];
    const float* wv = (const float*)d_in[5];
    const float* bv = (const float*)d_in[6];
    float* out = (float*)d_out;

    int use_ext = ((size_t)out_size >= OUT_ELEMS + PATT_ELEMS) ? 1 : 0;
    float* Pext = out + OUT_ELEMS;

    {   // K1: QKV -> fp16 (V transposed)
        dim3 grid(DMODEL / 128, (BATCH * SEQ) / 128, 3);
        qkv_kernel<<<grid, 256>>>(x, wq, bq, wk, bk, wv, bv);
    }
    {   // K2 fused: two-phase fp16 HMMA attention -> p (final) + out
        dim3 grid((SEQ + 127) / 128, BH);
        attn_kernel<<<grid, 256>>>(Pext, use_ext, out);
    }
}

// round 8
// speedup vs baseline: 3.5706x; 1.0688x over previous
#include <cuda_runtime.h>
#include <cuda_fp16.h>
#include <math.h>
#include <stdint.h>

#define BATCH 8
#define SEQ 1600
#define IN_DIM 256
#define DMODEL 512
#define NHEAD 8
#define HDIM 64
#define NJOINT 25
#define BH (BATCH*NHEAD)                 // 64
#define OUT_ELEMS (BATCH*SEQ*DMODEL)     // 6,553,600
#define PATT_ELEMS ((size_t)BH*SEQ*SEQ)  // 163,840,000

// scratch (__device__ globals; no allocation allowed)
__device__ __half g_q16[BH*SEQ*HDIM];
__device__ __half g_k16[BH*SEQ*HDIM];
__device__ __half g_vt16[BH*HDIM*SEQ];   // transposed: [bh][d][s]
__device__ float g_scores_fallback[PATT_ELEMS];

#define SW(o) ((o) ^ (((o) >> 3) & 0x70))

__device__ __forceinline__ uint32_t smem_u32(const void* p) {
    uint32_t a;
    asm("{ .reg .u64 t; cvta.to.shared.u64 t, %1; cvt.u32.u64 %0, t; }" : "=r"(a) : "l"(p));
    return a;
}
__device__ __forceinline__ void ldsm4(uint32_t* r, uint32_t addr) {
    asm volatile("ldmatrix.sync.aligned.m8n8.x4.shared.b16 {%0,%1,%2,%3}, [%4];"
                 : "=r"(r[0]), "=r"(r[1]), "=r"(r[2]), "=r"(r[3]) : "r"(addr));
}
__device__ __forceinline__ void mma16816(float* c, const uint32_t* a, const uint32_t* b) {
    asm volatile("mma.sync.aligned.m16n8k16.row.col.f32.f16.f16.f32 "
                 "{%0,%1,%2,%3}, {%4,%5,%6,%7}, {%8,%9}, {%0,%1,%2,%3};"
                 : "+f"(c[0]), "+f"(c[1]), "+f"(c[2]), "+f"(c[3])
                 : "r"(a[0]), "r"(a[1]), "r"(a[2]), "r"(a[3]), "r"(b[0]), "r"(b[1]));
}
__device__ __forceinline__ void cpasync16(uint32_t dst, const void* src) {
    asm volatile("cp.async.cg.shared.global [%0], [%1], 16;" :: "r"(dst), "l"(src));
}
__device__ __forceinline__ void cp_commit() { asm volatile("cp.async.commit_group;"); }
__device__ __forceinline__ void cp_wait1() { asm volatile("cp.async.wait_group 1;"); }
__device__ __forceinline__ void cp_wait0() { asm volatile("cp.async.wait_group 0;"); }

// ---------------------------------------------------------------------------
// K1: QKV projection (fp32 SIMT GEMM 128x128 tile). Epilogue emits fp16:
//   Q,K -> [bh, s, d];  V(+ReLU) -> transposed [bh, d, s].
// ---------------------------------------------------------------------------
__global__ __launch_bounds__(256, 2) void qkv_kernel(
    const float* __restrict__ x,
    const float* __restrict__ wq, const float* __restrict__ bq,
    const float* __restrict__ wk, const float* __restrict__ bk,
    const float* __restrict__ wv, const float* __restrict__ bv)
{
    const float* W; const float* bias; int z = blockIdx.z;
    if (z == 0)      { W = wq; bias = bq; }
    else if (z == 1) { W = wk; bias = bk; }
    else             { W = wv; bias = bv; }

    __shared__ float xsT[32][132];
    __shared__ float ws[32][132];

    const int t  = threadIdx.x;
    const int tx = t & 15, ty = t >> 4;
    const int rowBase = blockIdx.y * 128;
    const int nBase   = blockIdx.x * 128;

    float acc[8][8] = {};

    for (int k0 = 0; k0 < IN_DIM; k0 += 32) {
        float4 av[4], bv4[4];
        #pragma unroll
        for (int p = 0; p < 4; p++) {
            int idx = t + p * 256;
            int r   = idx >> 3;
            int cg  = (idx & 7) * 4;
            av[p] = *(const float4*)&x[(size_t)(rowBase + r) * IN_DIM + k0 + cg];
            int kk = idx >> 5;
            int c  = (idx & 31) * 4;
            bv4[p] = *(const float4*)&W[(size_t)(k0 + kk) * DMODEL + nBase + c];
        }
        __syncthreads();
        #pragma unroll
        for (int p = 0; p < 4; p++) {
            int idx = t + p * 256;
            int r   = idx >> 3;
            int cg  = (idx & 7) * 4;
            xsT[cg + 0][r] = av[p].x; xsT[cg + 1][r] = av[p].y;
            xsT[cg + 2][r] = av[p].z; xsT[cg + 3][r] = av[p].w;
            int kk = idx >> 5;
            int c  = (idx & 31) * 4;
            *(float4*)&ws[kk][c] = bv4[p];
        }
        __syncthreads();
        #pragma unroll
        for (int kk = 0; kk < 32; kk++) {
            float4 A0 = *(float4*)&xsT[kk][ty * 8];
            float4 A1 = *(float4*)&xsT[kk][ty * 8 + 4];
            float4 B0 = *(float4*)&ws[kk][tx * 8];
            float4 B1 = *(float4*)&ws[kk][tx * 8 + 4];
            float ar[8] = {A0.x,A0.y,A0.z,A0.w,A1.x,A1.y,A1.z,A1.w};
            float br[8] = {B0.x,B0.y,B0.z,B0.w,B1.x,B1.y,B1.z,B1.w};
            #pragma unroll
            for (int i = 0; i < 8; i++)
                #pragma unroll
                for (int j = 0; j < 8; j++)
                    acc[i][j] += ar[i] * br[j];
        }
    }

    float bb[8];
    #pragma unroll
    for (int j = 0; j < 8; j++) bb[j] = bias[nBase + tx * 8 + j];
    const int h  = (nBase + tx * 8) >> 6;
    const int ch = (nBase + tx * 8) & 63;

    if (z < 2) {
        __half* D = (z == 0) ? g_q16 : g_k16;
        #pragma unroll
        for (int i = 0; i < 8; i++) {
            int r  = rowBase + ty * 8 + i;
            int b_ = r / SEQ, s_ = r % SEQ;
            __align__(16) __half hb[8];
            #pragma unroll
            for (int j = 0; j < 8; j++)
                hb[j] = __float2half_rn(acc[i][j] + bb[j]);
            size_t base = ((size_t)(b_ * NHEAD + h) * SEQ + s_) * HDIM + ch;
            *(uint4*)&D[base] = *(uint4*)hb;
        }
    } else {
        int r0 = rowBase + ty * 8;
        int b_ = r0 / SEQ, s0 = r0 % SEQ;   // 8-row group never splits a batch
        #pragma unroll
        for (int j = 0; j < 8; j++) {
            __align__(16) __half hb[8];
            #pragma unroll
            for (int i = 0; i < 8; i++)
                hb[i] = __float2half_rn(fmaxf(acc[i][j] + bb[j], 0.f));  // ReLU
            size_t base = ((size_t)(b_ * NHEAD + h) * HDIM + (ch + j)) * SEQ + s0;
            *(uint4*)&g_vt16[base] = *(uint4*)hb;
        }
    }
}

// ---------------------------------------------------------------------------
// K2 fused: fp16 HMMA attention, two-phase, cp.async double-buffered,
// warp-uniform tile-level mask skip (a warp's 16 q rows span <=2 frames, so
// at most 2 of the 25 key tiles need per-element masking).
// ---------------------------------------------------------------------------
__global__ __launch_bounds__(256, 2) void attn_kernel(
    float* __restrict__ Pext, int use_ext, float* __restrict__ out)
{
    __shared__ __align__(16) __half sk[2][64*64];
    __shared__ __align__(16) __half sv[2][64*64];

    float* P = use_ext ? Pext : g_scores_fallback;
    const int tid = threadIdx.x, w = tid >> 5, lane = tid & 31;
    const int bh = blockIdx.y;
    const int qBase = blockIdx.x * 128;

    const int row0 = qBase + w * 16 + (lane >> 2);
    const int row1 = row0 + 8;
    const int c2   = (lane & 3) * 2;
    const int lo0 = (row0 / NJOINT) * NJOINT, hi0 = lo0 + NJOINT;
    const int lo1 = (row1 / NJOINT) * NJOINT, hi1 = lo1 + NJOINT;
    // warp-level masked key range: frames of rows [qBase+16w, +16)
    const int wrow = qBase + w * 16;
    const int loW = (wrow / NJOINT) * NJOINT;
    const int hiW = ((wrow + 15) / NJOINT) * NJOINT + NJOINT;

    const __half* q = g_q16 + (size_t)bh * SEQ * HDIM;
    const char* kB = (const char*)(g_k16 + (size_t)bh * SEQ * HDIM);
    const char* vB = (const char*)(g_vt16 + (size_t)bh * HDIM * SEQ);

    // Q A-fragments resident all kernel: qf[t] covers d=[16t,16t+16)
    uint32_t qf[4][4];
    {
        int r0c = min(row0, SEQ - 1), r1c = min(row1, SEQ - 1);
        #pragma unroll
        for (int t = 0; t < 4; t++) {
            qf[t][0] = *(const uint32_t*)&q[(size_t)r0c * HDIM + t*16 + c2];
            qf[t][1] = *(const uint32_t*)&q[(size_t)r1c * HDIM + t*16 + c2];
            qf[t][2] = *(const uint32_t*)&q[(size_t)r0c * HDIM + t*16 + 8 + c2];
            qf[t][3] = *(const uint32_t*)&q[(size_t)r1c * HDIM + t*16 + 8 + c2];
        }
    }

    const uint32_t sk_b = smem_u32(sk), sv_b = smem_u32(sv);

    // hoisted per-thread geometry
    uint32_t dstoff[2]; uint32_t srcKoff[2], srcVoff[2];
    #pragma unroll
    for (int p = 0; p < 2; p++) {
        int i = tid + p * 256;
        int r = i >> 3, cb = (i & 7) * 16;
        dstoff[p]  = SW(r * 128 + cb);
        srcKoff[p] = r * 128 + cb;          // + kt*8192
        srcVoff[p] = r * (SEQ * 2) + cb;    // + kt*128
    }
    const int lrow = lane & 7;
    const int lcb  = (lane >> 3) * 16;
    uint32_t lof[8];
    #pragma unroll
    for (int j = 0; j < 8; j++) lof[j] = SW((j * 8 + lrow) * 128 + lcb);

    float rsum0 = 0.f, rsum1 = 0.f;

    // ================= Phase A: rowsum only =================
    #pragma unroll
    for (int p = 0; p < 2; p++)
        cpasync16(sk_b + dstoff[p], kB + srcKoff[p]);
    cp_commit();

    #pragma unroll 1
    for (int kt = 0; kt < 25; kt++) {
        const int k0 = kt * 64;
        const uint32_t cb_ = sk_b + (kt & 1) * 8192;
        if (kt + 1 < 25) {
            const uint32_t nb = sk_b + ((kt + 1) & 1) * 8192;
            #pragma unroll
            for (int p = 0; p < 2; p++)
                cpasync16(nb + dstoff[p], kB + (kt + 1) * 8192 + srcKoff[p]);
            cp_commit();
            cp_wait1();
        } else cp_wait0();
        __syncthreads();

        const bool needMask = (k0 < hiW) && (k0 + 64 > loW);

        #pragma unroll
        for (int jp = 0; jp < 4; jp++) {
            uint32_t b0[8], b1[8];
            {
                uint32_t a = cb_ + lof[jp * 2];
                ldsm4(b0, a); ldsm4(b0 + 4, a ^ 64);
                uint32_t b = cb_ + lof[jp * 2 + 1];
                ldsm4(b1, b); ldsm4(b1 + 4, b ^ 64);
            }
            float c0[4] = {0.f,0.f,0.f,0.f}, c1[4] = {0.f,0.f,0.f,0.f};
            #pragma unroll
            for (int t = 0; t < 4; t++) {
                mma16816(c0, qf[t], b0 + 2*t);
                mma16816(c1, qf[t], b1 + 2*t);
            }
            if (needMask) {
                #pragma unroll
                for (int jj = 0; jj < 2; jj++) {
                    const float* cc = jj ? c1 : c0;
                    int ka = k0 + (jp * 2 + jj) * 8 + c2, kb2 = ka + 1;
                    bool a00 = (ka  < lo0) | (ka  >= hi0) | (ka  == row0);
                    bool a01 = (kb2 < lo0) | (kb2 >= hi0) | (kb2 == row0);
                    bool a10 = (ka  < lo1) | (ka  >= hi1) | (ka  == row1);
                    bool a11 = (kb2 < lo1) | (kb2 >= hi1) | (kb2 == row1);
                    rsum0 += (a00 ? __expf(cc[0] * 0.125f) : 0.f)
                           + (a01 ? __expf(cc[1] * 0.125f) : 0.f);
                    rsum1 += (a10 ? __expf(cc[2] * 0.125f) : 0.f)
                           + (a11 ? __expf(cc[3] * 0.125f) : 0.f);
                }
            } else {
                rsum0 += __expf(c0[0] * 0.125f) + __expf(c0[1] * 0.125f)
                       + __expf(c1[0] * 0.125f) + __expf(c1[1] * 0.125f);
                rsum1 += __expf(c0[2] * 0.125f) + __expf(c0[3] * 0.125f)
                       + __expf(c1[2] * 0.125f) + __expf(c1[3] * 0.125f);
            }
        }
        __syncthreads();
    }

    #pragma unroll
    for (int off = 1; off < 4; off <<= 1) {
        rsum0 += __shfl_xor_sync(0xffffffffu, rsum0, off);
        rsum1 += __shfl_xor_sync(0xffffffffu, rsum1, off);
    }
    const float inv0 = (row0 < SEQ) ? 1.f / rsum0 : 0.f;
    const float inv1 = (row1 < SEQ) ? 1.f / rsum1 : 0.f;

    float* prow0 = P + ((size_t)bh * SEQ + row0) * SEQ;   // deref only if row<SEQ
    float* prow1 = P + ((size_t)bh * SEQ + row1) * SEQ;

    float oc[8][4];
    #pragma unroll
    for (int j = 0; j < 8; j++) { oc[j][0]=0.f; oc[j][1]=0.f; oc[j][2]=0.f; oc[j][3]=0.f; }

    // ================= Phase B: recompute, write p, O += pV =================
    #pragma unroll
    for (int p = 0; p < 2; p++) {
        cpasync16(sk_b + dstoff[p], kB + srcKoff[p]);
        cpasync16(sv_b + dstoff[p], vB + srcVoff[p]);
    }
    cp_commit();

    #pragma unroll 1
    for (int kt = 0; kt < 25; kt++) {
        const int k0 = kt * 64;
        const uint32_t ckb = sk_b + (kt & 1) * 8192;
        const uint32_t cvb = sv_b + (kt & 1) * 8192;
        if (kt + 1 < 25) {
            const uint32_t off = ((kt + 1) & 1) * 8192;
            #pragma unroll
            for (int p = 0; p < 2; p++) {
                cpasync16(sk_b + off + dstoff[p], kB + (kt + 1) * 8192 + srcKoff[p]);
                cpasync16(sv_b + off + dstoff[p], vB + (kt + 1) * 128  + srcVoff[p]);
            }
            cp_commit();
            cp_wait1();
        } else cp_wait0();
        __syncthreads();

        const bool needMask = (k0 < hiW) && (k0 + 64 > loW);

        uint32_t pa[4][4];
        #pragma unroll
        for (int jp = 0; jp < 4; jp++) {
            uint32_t b0[8], b1[8];
            {
                uint32_t a = ckb + lof[jp * 2];
                ldsm4(b0, a); ldsm4(b0 + 4, a ^ 64);
                uint32_t b = ckb + lof[jp * 2 + 1];
                ldsm4(b1, b); ldsm4(b1 + 4, b ^ 64);
            }
            float c0[4] = {0.f,0.f,0.f,0.f}, c1[4] = {0.f,0.f,0.f,0.f};
            #pragma unroll
            for (int t = 0; t < 4; t++) {
                mma16816(c0, qf[t], b0 + 2*t);
                mma16816(c1, qf[t], b1 + 2*t);
            }
            if (needMask) {
                #pragma unroll
                for (int jj = 0; jj < 2; jj++) {
                    const float* cc = jj ? c1 : c0;
                    int ka = k0 + (jp * 2 + jj) * 8 + c2, kb2 = ka + 1;
                    bool a00 = (ka  < lo0) | (ka  >= hi0) | (ka  == row0);
                    bool a01 = (kb2 < lo0) | (kb2 >= hi0) | (kb2 == row0);
                    bool a10 = (ka  < lo1) | (ka  >= hi1) | (ka  == row1);
                    bool a11 = (kb2 < lo1) | (kb2 >= hi1) | (kb2 == row1);
                    float p00 = a00 ? __expf(cc[0] * 0.125f) * inv0 : 0.f;
                    float p01 = a01 ? __expf(cc[1] * 0.125f) * inv0 : 0.f;
                    float p10 = a10 ? __expf(cc[2] * 0.125f) * inv1 : 0.f;
                    float p11 = a11 ? __expf(cc[3] * 0.125f) * inv1 : 0.f;
                    if (row0 < SEQ) *(float2*)&prow0[ka] = make_float2(p00, p01);
                    if (row1 < SEQ) *(float2*)&prow1[ka] = make_float2(p10, p11);
                    __half2 h0 = __floats2half2_rn(p00, p01);
                    __half2 h1 = __floats2half2_rn(p10, p11);
                    pa[jp][jj * 2 + 0] = *(uint32_t*)&h0;
                    pa[jp][jj * 2 + 1] = *(uint32_t*)&h1;
                }
            } else {
                #pragma unroll
                for (int jj = 0; jj < 2; jj++) {
                    const float* cc = jj ? c1 : c0;
                    int ka = k0 + (jp * 2 + jj) * 8 + c2;
                    float p00 = __expf(cc[0] * 0.125f) * inv0;
                    float p01 = __expf(cc[1] * 0.125f) * inv0;
                    float p10 = __expf(cc[2] * 0.125f) * inv1;
                    float p11 = __expf(cc[3] * 0.125f) * inv1;
                    if (row0 < SEQ) *(float2*)&prow0[ka] = make_float2(p00, p01);
                    if (row1 < SEQ) *(float2*)&prow1[ka] = make_float2(p10, p11);
                    __half2 h0 = __floats2half2_rn(p00, p01);
                    __half2 h1 = __floats2half2_rn(p10, p11);
                    pa[jp][jj * 2 + 0] = *(uint32_t*)&h0;
                    pa[jp][jj * 2 + 1] = *(uint32_t*)&h1;
                }
            }
        }

        #pragma unroll
        for (int jp = 0; jp < 4; jp++) {
            uint32_t b0[8], b1[8];
            {
                uint32_t a = cvb + lof[jp * 2];
                ldsm4(b0, a); ldsm4(b0 + 4, a ^ 64);
                uint32_t b = cvb + lof[jp * 2 + 1];
                ldsm4(b1, b); ldsm4(b1 + 4, b ^ 64);
            }
            #pragma unroll
            for (int t = 0; t < 4; t++) {
                mma16816(oc[jp * 2],     pa[t], b0 + 2*t);
                mma16816(oc[jp * 2 + 1], pa[t], b1 + 2*t);
            }
        }
        __syncthreads();
    }

    const int b_ = bh >> 3, h_ = bh & 7;
    float* ob0 = out + ((size_t)b_ * SEQ + row0) * DMODEL + h_ * HDIM;
    float* ob1 = out + ((size_t)b_ * SEQ + row1) * DMODEL + h_ * HDIM;
    #pragma unroll
    for (int j = 0; j < 8; j++) {
        if (row0 < SEQ) *(float2*)&ob0[j * 8 + c2] = make_float2(oc[j][0], oc[j][1]);
        if (row1 < SEQ) *(float2*)&ob1[j * 8 + c2] = make_float2(oc[j][2], oc[j][3]);
    }
}

// ---------------------------------------------------------------------------
extern "C" void kernel_launch(void* const* d_in, const int* in_sizes, int n_in,
                              void* d_out, int out_size)
{
    const float* x  = (const float*)d_in[0];
    const float* wq = (const float*)d_in[1];
    const float* bq = (const float*)d_in[2];
    const float* wk = (const float*)d_in[3];
    const float* bk = (const float*)d_in[4];
    const float* wv = (const float*)d_in[5];
    const float* bv = (const float*)d_in[6];
    float* out = (float*)d_out;

    int use_ext = ((size_t)out_size >= OUT_ELEMS + PATT_ELEMS) ? 1 : 0;
    float* Pext = out + OUT_ELEMS;

    {   // K1: QKV -> fp16 (V transposed)
        dim3 grid(DMODEL / 128, (BATCH * SEQ) / 128, 3);
        qkv_kernel<<<grid, 256>>>(x, wq, bq, wk, bk, wv, bv);
    }
    {   // K2 fused: two-phase fp16 HMMA attention -> p (final) + out
        dim3 grid((SEQ + 127) / 128, BH);
        attn_kernel<<<grid, 256>>>(Pext, use_ext, out);
    }
}

// round 9
// speedup vs baseline: 3.9157x; 1.0967x over previous
#include <cuda_runtime.h>
#include <cuda_fp16.h>
#include <math.h>
#include <stdint.h>

#define BATCH 8
#define SEQ 1600
#define IN_DIM 256
#define DMODEL 512
#define NHEAD 8
#define HDIM 64
#define NJOINT 25
#define BH (BATCH*NHEAD)                 // 64
#define OUT_ELEMS (BATCH*SEQ*DMODEL)     // 6,553,600
#define PATT_ELEMS ((size_t)BH*SEQ*SEQ)  // 163,840,000

// scratch (__device__ globals; no allocation allowed)
__device__ __half g_q16[BH*SEQ*HDIM];
__device__ __half g_k16[BH*SEQ*HDIM];
__device__ __half g_vt16[BH*HDIM*SEQ];   // transposed: [bh][d][s]
__device__ float g_scores_fallback[PATT_ELEMS];

#define SW(o) ((o) ^ (((o) >> 3) & 0x70))

__device__ __forceinline__ uint32_t smem_u32(const void* p) {
    uint32_t a;
    asm("{ .reg .u64 t; cvta.to.shared.u64 t, %1; cvt.u32.u64 %0, t; }" : "=r"(a) : "l"(p));
    return a;
}
__device__ __forceinline__ void ldsm4(uint32_t* r, uint32_t addr) {
    asm volatile("ldmatrix.sync.aligned.m8n8.x4.shared.b16 {%0,%1,%2,%3}, [%4];"
                 : "=r"(r[0]), "=r"(r[1]), "=r"(r[2]), "=r"(r[3]) : "r"(addr));
}
__device__ __forceinline__ void mma16816(float* c, const uint32_t* a, const uint32_t* b) {
    asm volatile("mma.sync.aligned.m16n8k16.row.col.f32.f16.f16.f32 "
                 "{%0,%1,%2,%3}, {%4,%5,%6,%7}, {%8,%9}, {%0,%1,%2,%3};"
                 : "+f"(c[0]), "+f"(c[1]), "+f"(c[2]), "+f"(c[3])
                 : "r"(a[0]), "r"(a[1]), "r"(a[2]), "r"(a[3]), "r"(b[0]), "r"(b[1]));
}
__device__ __forceinline__ void cpasync16(uint32_t dst, const void* src) {
    asm volatile("cp.async.cg.shared.global [%0], [%1], 16;" :: "r"(dst), "l"(src));
}
__device__ __forceinline__ void cp_commit() { asm volatile("cp.async.commit_group;"); }
__device__ __forceinline__ void cp_wait1() { asm volatile("cp.async.wait_group 1;"); }
__device__ __forceinline__ void cp_wait0() { asm volatile("cp.async.wait_group 0;"); }

// ---------------------------------------------------------------------------
// K1: QKV projection, mixed path.
//  z=0,1 (Q,K): split-fp16 HMMA GEMM (3 terms: AhBh + AhBl + AlBh), ~1e-6 acc.
//  z=2   (V):   fp32 SIMT GEMM (128x128 tile) with ReLU + transposed epilogue.
// Epilogue emits fp16: Q,K -> [bh, s, d]; V -> [bh, d, s].
// ---------------------------------------------------------------------------
// smem union: HMMA needs 4 * 128*24 halves (24.6KB); SIMT needs 2*32*132 f32 (33.8KB)
#define QKV_SMEM_BYTES 33792

__global__ __launch_bounds__(256, 2) void qkv_kernel(
    const float* __restrict__ x,
    const float* __restrict__ wq, const float* __restrict__ bq,
    const float* __restrict__ wk, const float* __restrict__ bk,
    const float* __restrict__ wv, const float* __restrict__ bv)
{
    __shared__ __align__(16) char smraw[QKV_SMEM_BYTES];
    const int z = blockIdx.z;
    const int t = threadIdx.x;

    if (z == 2) {
        // ================== V: fp32 SIMT path (ReLU + transpose) ==================
        float (*xsT)[132] = (float(*)[132])smraw;
        float (*ws)[132]  = (float(*)[132])(smraw + 32 * 132 * 4);
        const float* W = wv; const float* bias = bv;

        const int tx = t & 15, ty = t >> 4;
        const int rowBase = blockIdx.y * 128;
        const int nBase   = blockIdx.x * 128;

        float acc[8][8] = {};

        for (int k0 = 0; k0 < IN_DIM; k0 += 32) {
            float4 av[4], bv4[4];
            #pragma unroll
            for (int p = 0; p < 4; p++) {
                int idx = t + p * 256;
                int r   = idx >> 3;
                int cg  = (idx & 7) * 4;
                av[p] = *(const float4*)&x[(size_t)(rowBase + r) * IN_DIM + k0 + cg];
                int kk = idx >> 5;
                int c  = (idx & 31) * 4;
                bv4[p] = *(const float4*)&W[(size_t)(k0 + kk) * DMODEL + nBase + c];
            }
            __syncthreads();
            #pragma unroll
            for (int p = 0; p < 4; p++) {
                int idx = t + p * 256;
                int r   = idx >> 3;
                int cg  = (idx & 7) * 4;
                xsT[cg + 0][r] = av[p].x; xsT[cg + 1][r] = av[p].y;
                xsT[cg + 2][r] = av[p].z; xsT[cg + 3][r] = av[p].w;
                int kk = idx >> 5;
                int c  = (idx & 31) * 4;
                *(float4*)&ws[kk][c] = bv4[p];
            }
            __syncthreads();
            #pragma unroll
            for (int kk = 0; kk < 32; kk++) {
                float4 A0 = *(float4*)&xsT[kk][ty * 8];
                float4 A1 = *(float4*)&xsT[kk][ty * 8 + 4];
                float4 B0 = *(float4*)&ws[kk][tx * 8];
                float4 B1 = *(float4*)&ws[kk][tx * 8 + 4];
                float ar[8] = {A0.x,A0.y,A0.z,A0.w,A1.x,A1.y,A1.z,A1.w};
                float br[8] = {B0.x,B0.y,B0.z,B0.w,B1.x,B1.y,B1.z,B1.w};
                #pragma unroll
                for (int i = 0; i < 8; i++)
                    #pragma unroll
                    for (int j = 0; j < 8; j++)
                        acc[i][j] += ar[i] * br[j];
            }
        }

        float bb[8];
        #pragma unroll
        for (int j = 0; j < 8; j++) bb[j] = bias[nBase + tx * 8 + j];
        const int h  = (nBase + tx * 8) >> 6;
        const int ch = (nBase + tx * 8) & 63;

        int r0 = rowBase + ty * 8;
        int b_ = r0 / SEQ, s0 = r0 % SEQ;   // 8-row group never splits a batch
        #pragma unroll
        for (int j = 0; j < 8; j++) {
            __align__(16) __half hb[8];
            #pragma unroll
            for (int i = 0; i < 8; i++)
                hb[i] = __float2half_rn(fmaxf(acc[i][j] + bb[j], 0.f));  // ReLU
            size_t base = ((size_t)(b_ * NHEAD + h) * HDIM + (ch + j)) * SEQ + s0;
            *(uint4*)&g_vt16[base] = *(uint4*)hb;
        }
        return;
    }

    // ================== Q/K: split-fp16 HMMA path ==================
    __half* xh = (__half*)smraw;              // [128][24] halves, 48B pitch
    __half* xl = (__half*)(smraw + 6144);
    __half* wh = (__half*)(smraw + 12288);    // [n=128][24]
    __half* wl = (__half*)(smraw + 18432);

    const float* W    = (z == 0) ? wq : wk;
    const float* bias = (z == 0) ? bq : bk;
    __half* D         = (z == 0) ? g_q16 : g_k16;

    const int w = t >> 5, lane = t & 31;
    const int rowBase = blockIdx.y * 128;
    const int nBase   = blockIdx.x * 128;

    const uint32_t xh_b = smem_u32(xh), xl_b = smem_u32(xl);
    const uint32_t wh_b = smem_u32(wh), wl_b = smem_u32(wl);

    // A-frag lane addressing: m0=(r0-7,k0-7) m1=(r8-15,k0-7) m2=(r0-7,k8-15) m3
    const int ar  = (lane & 7) + ((lane >> 3) & 1) * 8;
    const int akb = (lane >> 4) * 16;
    const uint32_t aoff = (uint32_t)((w * 16 + ar) * 48 + akb);
    // B-frag lane addressing: m0=(n0-7,k0-7) m1=(n0-7,k8-15) m2=(n8-15,k0-7) m3
    const int bn  = (lane & 7) + ((lane >> 4) & 1) * 8;
    const int bkb = ((lane >> 3) & 1) * 16;
    uint32_t boff[8];
    #pragma unroll
    for (int jp = 0; jp < 8; jp++) boff[jp] = (uint32_t)((jp * 16 + bn) * 48 + bkb);

    float oc[16][4];
    #pragma unroll
    for (int j = 0; j < 16; j++) { oc[j][0]=0.f; oc[j][1]=0.f; oc[j][2]=0.f; oc[j][3]=0.f; }

    // per-thread load geometry
    float4 xv[2]; float wvv[2][4];
    int xrow[2], xseg[2], wcol[2], wk4[2];
    #pragma unroll
    for (int p = 0; p < 2; p++) {
        int idx = t + p * 256;
        xrow[p] = idx >> 2; xseg[p] = idx & 3;
        wcol[p] = idx & 127; wk4[p] = (idx >> 7) * 4;
    }

    // prologue: load chunk 0
    #pragma unroll
    for (int p = 0; p < 2; p++) {
        xv[p] = *(const float4*)&x[(size_t)(rowBase + xrow[p]) * IN_DIM + xseg[p] * 4];
        #pragma unroll
        for (int i = 0; i < 4; i++)
            wvv[p][i] = W[(size_t)(wk4[p] + i) * DMODEL + nBase + wcol[p]];
    }

    #pragma unroll 1
    for (int kc = 0; kc < 16; kc++) {
        __syncthreads();
        // convert + store chunk to smem (hi/lo)
        #pragma unroll
        for (int p = 0; p < 2; p++) {
            float vv[4] = {xv[p].x, xv[p].y, xv[p].z, xv[p].w};
            __align__(8) __half hs[4], ls[4];
            #pragma unroll
            for (int i = 0; i < 4; i++) {
                hs[i] = __float2half_rn(vv[i]);
                ls[i] = __float2half_rn(vv[i] - __half2float(hs[i]));
            }
            *(uint2*)&xh[xrow[p] * 24 + xseg[p] * 4] = *(uint2*)hs;
            *(uint2*)&xl[xrow[p] * 24 + xseg[p] * 4] = *(uint2*)ls;
            __align__(8) __half whs[4], wls[4];
            #pragma unroll
            for (int i = 0; i < 4; i++) {
                whs[i] = __float2half_rn(wvv[p][i]);
                wls[i] = __float2half_rn(wvv[p][i] - __half2float(whs[i]));
            }
            *(uint2*)&wh[wcol[p] * 24 + wk4[p]] = *(uint2*)whs;
            *(uint2*)&wl[wcol[p] * 24 + wk4[p]] = *(uint2*)wls;
        }
        __syncthreads();

        // prefetch next chunk into regs (hidden under MMAs)
        if (kc + 1 < 16) {
            const int k0n = (kc + 1) * 16;
            #pragma unroll
            for (int p = 0; p < 2; p++) {
                xv[p] = *(const float4*)&x[(size_t)(rowBase + xrow[p]) * IN_DIM + k0n + xseg[p] * 4];
                #pragma unroll
                for (int i = 0; i < 4; i++)
                    wvv[p][i] = W[(size_t)(k0n + wk4[p] + i) * DMODEL + nBase + wcol[p]];
            }
        }

        uint32_t ah[4], al[4];
        ldsm4(ah, xh_b + aoff);
        ldsm4(al, xl_b + aoff);
        #pragma unroll
        for (int jp = 0; jp < 8; jp++) {
            uint32_t bh4[4], bl4[4];
            ldsm4(bh4, wh_b + boff[jp]);
            ldsm4(bl4, wl_b + boff[jp]);
            mma16816(oc[2*jp],     ah, bh4);
            mma16816(oc[2*jp + 1], ah, bh4 + 2);
            mma16816(oc[2*jp],     ah, bl4);
            mma16816(oc[2*jp + 1], ah, bl4 + 2);
            mma16816(oc[2*jp],     al, bh4);
            mma16816(oc[2*jp + 1], al, bh4 + 2);
        }
    }

    // epilogue: +bias, fp16, store to [bh][s][d]
    const int c2 = (lane & 3) * 2;
    const int row0 = rowBase + w * 16 + (lane >> 2);
    const int row1 = row0 + 8;
    const int b0_ = row0 / SEQ, s0 = row0 - b0_ * SEQ;
    const int b1_ = row1 / SEQ, s1 = row1 - b1_ * SEQ;
    #pragma unroll
    for (int j = 0; j < 16; j++) {
        int col = nBase + j * 8 + c2;
        int h = col >> 6, ch = col & 63;
        float bb0 = bias[col], bb1 = bias[col + 1];
        __half2 v0 = __floats2half2_rn(oc[j][0] + bb0, oc[j][1] + bb1);
        __half2 v1 = __floats2half2_rn(oc[j][2] + bb0, oc[j][3] + bb1);
        *(__half2*)&D[((size_t)(b0_ * NHEAD + h) * SEQ + s0) * HDIM + ch] = v0;
        *(__half2*)&D[((size_t)(b1_ * NHEAD + h) * SEQ + s1) * HDIM + ch] = v1;
    }
}

// ---------------------------------------------------------------------------
// K2 fused: fp16 HMMA attention, two-phase, cp.async double-buffered,
// warp-uniform tile-level mask skip. (unchanged from previous round)
// ---------------------------------------------------------------------------
__global__ __launch_bounds__(256, 2) void attn_kernel(
    float* __restrict__ Pext, int use_ext, float* __restrict__ out)
{
    __shared__ __align__(16) __half sk[2][64*64];
    __shared__ __align__(16) __half sv[2][64*64];

    float* P = use_ext ? Pext : g_scores_fallback;
    const int tid = threadIdx.x, w = tid >> 5, lane = tid & 31;
    const int bh = blockIdx.y;
    const int qBase = blockIdx.x * 128;

    const int row0 = qBase + w * 16 + (lane >> 2);
    const int row1 = row0 + 8;
    const int c2   = (lane & 3) * 2;
    const int lo0 = (row0 / NJOINT) * NJOINT, hi0 = lo0 + NJOINT;
    const int lo1 = (row1 / NJOINT) * NJOINT, hi1 = lo1 + NJOINT;
    const int wrow = qBase + w * 16;
    const int loW = (wrow / NJOINT) * NJOINT;
    const int hiW = ((wrow + 15) / NJOINT) * NJOINT + NJOINT;

    const __half* q = g_q16 + (size_t)bh * SEQ * HDIM;
    const char* kB = (const char*)(g_k16 + (size_t)bh * SEQ * HDIM);
    const char* vB = (const char*)(g_vt16 + (size_t)bh * HDIM * SEQ);

    uint32_t qf[4][4];
    {
        int r0c = min(row0, SEQ - 1), r1c = min(row1, SEQ - 1);
        #pragma unroll
        for (int t = 0; t < 4; t++) {
            qf[t][0] = *(const uint32_t*)&q[(size_t)r0c * HDIM + t*16 + c2];
            qf[t][1] = *(const uint32_t*)&q[(size_t)r1c * HDIM + t*16 + c2];
            qf[t][2] = *(const uint32_t*)&q[(size_t)r0c * HDIM + t*16 + 8 + c2];
            qf[t][3] = *(const uint32_t*)&q[(size_t)r1c * HDIM + t*16 + 8 + c2];
        }
    }

    const uint32_t sk_b = smem_u32(sk), sv_b = smem_u32(sv);

    uint32_t dstoff[2]; uint32_t srcKoff[2], srcVoff[2];
    #pragma unroll
    for (int p = 0; p < 2; p++) {
        int i = tid + p * 256;
        int r = i >> 3, cb = (i & 7) * 16;
        dstoff[p]  = SW(r * 128 + cb);
        srcKoff[p] = r * 128 + cb;
        srcVoff[p] = r * (SEQ * 2) + cb;
    }
    const int lrow = lane & 7;
    const int lcb  = (lane >> 3) * 16;
    uint32_t lof[8];
    #pragma unroll
    for (int j = 0; j < 8; j++) lof[j] = SW((j * 8 + lrow) * 128 + lcb);

    float rsum0 = 0.f, rsum1 = 0.f;

    // ================= Phase A: rowsum only =================
    #pragma unroll
    for (int p = 0; p < 2; p++)
        cpasync16(sk_b + dstoff[p], kB + srcKoff[p]);
    cp_commit();

    #pragma unroll 1
    for (int kt = 0; kt < 25; kt++) {
        const int k0 = kt * 64;
        const uint32_t cb_ = sk_b + (kt & 1) * 8192;
        if (kt + 1 < 25) {
            const uint32_t nb = sk_b + ((kt + 1) & 1) * 8192;
            #pragma unroll
            for (int p = 0; p < 2; p++)
                cpasync16(nb + dstoff[p], kB + (kt + 1) * 8192 + srcKoff[p]);
            cp_commit();
            cp_wait1();
        } else cp_wait0();
        __syncthreads();

        const bool needMask = (k0 < hiW) && (k0 + 64 > loW);

        #pragma unroll
        for (int jp = 0; jp < 4; jp++) {
            uint32_t b0[8], b1[8];
            {
                uint32_t a = cb_ + lof[jp * 2];
                ldsm4(b0, a); ldsm4(b0 + 4, a ^ 64);
                uint32_t b = cb_ + lof[jp * 2 + 1];
                ldsm4(b1, b); ldsm4(b1 + 4, b ^ 64);
            }
            float c0[4] = {0.f,0.f,0.f,0.f}, c1[4] = {0.f,0.f,0.f,0.f};
            #pragma unroll
            for (int t = 0; t < 4; t++) {
                mma16816(c0, qf[t], b0 + 2*t);
                mma16816(c1, qf[t], b1 + 2*t);
            }
            if (needMask) {
                #pragma unroll
                for (int jj = 0; jj < 2; jj++) {
                    const float* cc = jj ? c1 : c0;
                    int ka = k0 + (jp * 2 + jj) * 8 + c2, kb2 = ka + 1;
                    bool a00 = (ka  < lo0) | (ka  >= hi0) | (ka  == row0);
                    bool a01 = (kb2 < lo0) | (kb2 >= hi0) | (kb2 == row0);
                    bool a10 = (ka  < lo1) | (ka  >= hi1) | (ka  == row1);
                    bool a11 = (kb2 < lo1) | (kb2 >= hi1) | (kb2 == row1);
                    rsum0 += (a00 ? __expf(cc[0] * 0.125f) : 0.f)
                           + (a01 ? __expf(cc[1] * 0.125f) : 0.f);
                    rsum1 += (a10 ? __expf(cc[2] * 0.125f) : 0.f)
                           + (a11 ? __expf(cc[3] * 0.125f) : 0.f);
                }
            } else {
                rsum0 += __expf(c0[0] * 0.125f) + __expf(c0[1] * 0.125f)
                       + __expf(c1[0] * 0.125f) + __expf(c1[1] * 0.125f);
                rsum1 += __expf(c0[2] * 0.125f) + __expf(c0[3] * 0.125f)
                       + __expf(c1[2] * 0.125f) + __expf(c1[3] * 0.125f);
            }
        }
        __syncthreads();
    }

    #pragma unroll
    for (int off = 1; off < 4; off <<= 1) {
        rsum0 += __shfl_xor_sync(0xffffffffu, rsum0, off);
        rsum1 += __shfl_xor_sync(0xffffffffu, rsum1, off);
    }
    const float inv0 = (row0 < SEQ) ? 1.f / rsum0 : 0.f;
    const float inv1 = (row1 < SEQ) ? 1.f / rsum1 : 0.f;

    float* prow0 = P + ((size_t)bh * SEQ + row0) * SEQ;
    float* prow1 = P + ((size_t)bh * SEQ + row1) * SEQ;

    float oc[8][4];
    #pragma unroll
    for (int j = 0; j < 8; j++) { oc[j][0]=0.f; oc[j][1]=0.f; oc[j][2]=0.f; oc[j][3]=0.f; }

    // ================= Phase B: recompute, write p, O += pV =================
    #pragma unroll
    for (int p = 0; p < 2; p++) {
        cpasync16(sk_b + dstoff[p], kB + srcKoff[p]);
        cpasync16(sv_b + dstoff[p], vB + srcVoff[p]);
    }
    cp_commit();

    #pragma unroll 1
    for (int kt = 0; kt < 25; kt++) {
        const int k0 = kt * 64;
        const uint32_t ckb = sk_b + (kt & 1) * 8192;
        const uint32_t cvb = sv_b + (kt & 1) * 8192;
        if (kt + 1 < 25) {
            const uint32_t off = ((kt + 1) & 1) * 8192;
            #pragma unroll
            for (int p = 0; p < 2; p++) {
                cpasync16(sk_b + off + dstoff[p], kB + (kt + 1) * 8192 + srcKoff[p]);
                cpasync16(sv_b + off + dstoff[p], vB + (kt + 1) * 128  + srcVoff[p]);
            }
            cp_commit();
            cp_wait1();
        } else cp_wait0();
        __syncthreads();

        const bool needMask = (k0 < hiW) && (k0 + 64 > loW);

        uint32_t pa[4][4];
        #pragma unroll
        for (int jp = 0; jp < 4; jp++) {
            uint32_t b0[8], b1[8];
            {
                uint32_t a = ckb + lof[jp * 2];
                ldsm4(b0, a); ldsm4(b0 + 4, a ^ 64);
                uint32_t b = ckb + lof[jp * 2 + 1];
                ldsm4(b1, b); ldsm4(b1 + 4, b ^ 64);
            }
            float c0[4] = {0.f,0.f,0.f,0.f}, c1[4] = {0.f,0.f,0.f,0.f};
            #pragma unroll
            for (int t = 0; t < 4; t++) {
                mma16816(c0, qf[t], b0 + 2*t);
                mma16816(c1, qf[t], b1 + 2*t);
            }
            if (needMask) {
                #pragma unroll
                for (int jj = 0; jj < 2; jj++) {
                    const float* cc = jj ? c1 : c0;
                    int ka = k0 + (jp * 2 + jj) * 8 + c2, kb2 = ka + 1;
                    bool a00 = (ka  < lo0) | (ka  >= hi0) | (ka  == row0);
                    bool a01 = (kb2 < lo0) | (kb2 >= hi0) | (kb2 == row0);
                    bool a10 = (ka  < lo1) | (ka  >= hi1) | (ka  == row1);
                    bool a11 = (kb2 < lo1) | (kb2 >= hi1) | (kb2 == row1);
                    float p00 = a00 ? __expf(cc[0] * 0.125f) * inv0 : 0.f;
                    float p01 = a01 ? __expf(cc[1] * 0.125f) * inv0 : 0.f;
                    float p10 = a10 ? __expf(cc[2] * 0.125f) * inv1 : 0.f;
                    float p11 = a11 ? __expf(cc[3] * 0.125f) * inv1 : 0.f;
                    if (row0 < SEQ) *(float2*)&prow0[ka] = make_float2(p00, p01);
                    if (row1 < SEQ) *(float2*)&prow1[ka] = make_float2(p10, p11);
                    __half2 h0 = __floats2half2_rn(p00, p01);
                    __half2 h1 = __floats2half2_rn(p10, p11);
                    pa[jp][jj * 2 + 0] = *(uint32_t*)&h0;
                    pa[jp][jj * 2 + 1] = *(uint32_t*)&h1;
                }
            } else {
                #pragma unroll
                for (int jj = 0; jj < 2; jj++) {
                    const float* cc = jj ? c1 : c0;
                    int ka = k0 + (jp * 2 + jj) * 8 + c2;
                    float p00 = __expf(cc[0] * 0.125f) * inv0;
                    float p01 = __expf(cc[1] * 0.125f) * inv0;
                    float p10 = __expf(cc[2] * 0.125f) * inv1;
                    float p11 = __expf(cc[3] * 0.125f) * inv1;
                    if (row0 < SEQ) *(float2*)&prow0[ka] = make_float2(p00, p01);
                    if (row1 < SEQ) *(float2*)&prow1[ka] = make_float2(p10, p11);
                    __half2 h0 = __floats2half2_rn(p00, p01);
                    __half2 h1 = __floats2half2_rn(p10, p11);
                    pa[jp][jj * 2 + 0] = *(uint32_t*)&h0;
                    pa[jp][jj * 2 + 1] = *(uint32_t*)&h1;
                }
            }
        }

        #pragma unroll
        for (int jp = 0; jp < 4; jp++) {
            uint32_t b0[8], b1[8];
            {
                uint32_t a = cvb + lof[jp * 2];
                ldsm4(b0, a); ldsm4(b0 + 4, a ^ 64);
                uint32_t b = cvb + lof[jp * 2 + 1];
                ldsm4(b1, b); ldsm4(b1 + 4, b ^ 64);
            }
            #pragma unroll
            for (int t = 0; t < 4; t++) {
                mma16816(oc[jp * 2],     pa[t], b0 + 2*t);
                mma16816(oc[jp * 2 + 1], pa[t], b1 + 2*t);
            }
        }
        __syncthreads();
    }

    const int b_ = bh >> 3, h_ = bh & 7;
    float* ob0 = out + ((size_t)b_ * SEQ + row0) * DMODEL + h_ * HDIM;
    float* ob1 = out + ((size_t)b_ * SEQ + row1) * DMODEL + h_ * HDIM;
    #pragma unroll
    for (int j = 0; j < 8; j++) {
        if (row0 < SEQ) *(float2*)&ob0[j * 8 + c2] = make_float2(oc[j][0], oc[j][1]);
        if (row1 < SEQ) *(float2*)&ob1[j * 8 + c2] = make_float2(oc[j][2], oc[j][3]);
    }
}

// ---------------------------------------------------------------------------
extern "C" void kernel_launch(void* const* d_in, const int* in_sizes, int n_in,
                              void* d_out, int out_size)
{
    const float* x  = (const float*)d_in[0];
    const float* wq = (const float*)d_in[1];
    const float* bq = (const float*)d_in[2];
    const float* wk = (const float*)d_in[3];
    const float* bk = (const float*)d_in[4];
    const float* wv = (const float*)d_in[5];
    const float* bv = (const float*)d_in[6];
    float* out = (float*)d_out;

    int use_ext = ((size_t)out_size >= OUT_ELEMS + PATT_ELEMS) ? 1 : 0;
    float* Pext = out + OUT_ELEMS;

    {   // K1: QKV -> fp16 (Q,K via HMMA; V via SIMT, transposed)
        dim3 grid(DMODEL / 128, (BATCH * SEQ) / 128, 3);
        qkv_kernel<<<grid, 256>>>(x, wq, bq, wk, bk, wv, bv);
    }
    {   // K2 fused: two-phase fp16 HMMA attention -> p (final) + out
        dim3 grid((SEQ + 127) / 128, BH);
        attn_kernel<<<grid, 256>>>(Pext, use_ext, out);
    }
}

// round 10
// speedup vs baseline: 4.1662x; 1.0640x over previous
#include <cuda_runtime.h>
#include <cuda_fp16.h>
#include <math.h>
#include <stdint.h>

#define BATCH 8
#define SEQ 1600
#define IN_DIM 256
#define DMODEL 512
#define NHEAD 8
#define HDIM 64
#define NJOINT 25
#define BH (BATCH*NHEAD)                 // 64
#define OUT_ELEMS (BATCH*SEQ*DMODEL)     // 6,553,600
#define PATT_ELEMS ((size_t)BH*SEQ*SEQ)  // 163,840,000

// scratch (__device__ globals; no allocation allowed)
__device__ __half g_q16[BH*SEQ*HDIM];
__device__ __half g_k16[BH*SEQ*HDIM];
__device__ __half g_vt16[BH*HDIM*SEQ];   // transposed: [bh][d][s]
__device__ float g_scores_fallback[PATT_ELEMS];

#define SW(o) ((o) ^ (((o) >> 3) & 0x70))

__device__ __forceinline__ uint32_t smem_u32(const void* p) {
    uint32_t a;
    asm("{ .reg .u64 t; cvta.to.shared.u64 t, %1; cvt.u32.u64 %0, t; }" : "=r"(a) : "l"(p));
    return a;
}
__device__ __forceinline__ void ldsm4(uint32_t* r, uint32_t addr) {
    asm volatile("ldmatrix.sync.aligned.m8n8.x4.shared.b16 {%0,%1,%2,%3}, [%4];"
                 : "=r"(r[0]), "=r"(r[1]), "=r"(r[2]), "=r"(r[3]) : "r"(addr));
}
__device__ __forceinline__ void mma16816(float* c, const uint32_t* a, const uint32_t* b) {
    asm volatile("mma.sync.aligned.m16n8k16.row.col.f32.f16.f16.f32 "
                 "{%0,%1,%2,%3}, {%4,%5,%6,%7}, {%8,%9}, {%0,%1,%2,%3};"
                 : "+f"(c[0]), "+f"(c[1]), "+f"(c[2]), "+f"(c[3])
                 : "r"(a[0]), "r"(a[1]), "r"(a[2]), "r"(a[3]), "r"(b[0]), "r"(b[1]));
}
__device__ __forceinline__ void cpasync16(uint32_t dst, const void* src) {
    asm volatile("cp.async.cg.shared.global [%0], [%1], 16;" :: "r"(dst), "l"(src));
}
__device__ __forceinline__ void cp_commit() { asm volatile("cp.async.commit_group;"); }
__device__ __forceinline__ void cp_wait1() { asm volatile("cp.async.wait_group 1;"); }
__device__ __forceinline__ void cp_wait0() { asm volatile("cp.async.wait_group 0;"); }
__device__ __forceinline__ void stg_cs2(float* p, float a, float b) {
    asm volatile("st.global.cs.v2.f32 [%0], {%1, %2};" :: "l"(p), "f"(a), "f"(b) : "memory");
}

// ---------------------------------------------------------------------------
// K1: QKV projection, mixed path (unchanged from previous round).
//  z=0,1 (Q,K): split-fp16 HMMA GEMM (3 terms).  z=2 (V): fp32 SIMT + ReLU + T.
// ---------------------------------------------------------------------------
#define QKV_SMEM_BYTES 33792

__global__ __launch_bounds__(256, 2) void qkv_kernel(
    const float* __restrict__ x,
    const float* __restrict__ wq, const float* __restrict__ bq,
    const float* __restrict__ wk, const float* __restrict__ bk,
    const float* __restrict__ wv, const float* __restrict__ bv)
{
    __shared__ __align__(16) char smraw[QKV_SMEM_BYTES];
    const int z = blockIdx.z;
    const int t = threadIdx.x;

    if (z == 2) {
        float (*xsT)[132] = (float(*)[132])smraw;
        float (*ws)[132]  = (float(*)[132])(smraw + 32 * 132 * 4);
        const float* W = wv; const float* bias = bv;

        const int tx = t & 15, ty = t >> 4;
        const int rowBase = blockIdx.y * 128;
        const int nBase   = blockIdx.x * 128;

        float acc[8][8] = {};

        for (int k0 = 0; k0 < IN_DIM; k0 += 32) {
            float4 av[4], bv4[4];
            #pragma unroll
            for (int p = 0; p < 4; p++) {
                int idx = t + p * 256;
                int r   = idx >> 3;
                int cg  = (idx & 7) * 4;
                av[p] = *(const float4*)&x[(size_t)(rowBase + r) * IN_DIM + k0 + cg];
                int kk = idx >> 5;
                int c  = (idx & 31) * 4;
                bv4[p] = *(const float4*)&W[(size_t)(k0 + kk) * DMODEL + nBase + c];
            }
            __syncthreads();
            #pragma unroll
            for (int p = 0; p < 4; p++) {
                int idx = t + p * 256;
                int r   = idx >> 3;
                int cg  = (idx & 7) * 4;
                xsT[cg + 0][r] = av[p].x; xsT[cg + 1][r] = av[p].y;
                xsT[cg + 2][r] = av[p].z; xsT[cg + 3][r] = av[p].w;
                int kk = idx >> 5;
                int c  = (idx & 31) * 4;
                *(float4*)&ws[kk][c] = bv4[p];
            }
            __syncthreads();
            #pragma unroll
            for (int kk = 0; kk < 32; kk++) {
                float4 A0 = *(float4*)&xsT[kk][ty * 8];
                float4 A1 = *(float4*)&xsT[kk][ty * 8 + 4];
                float4 B0 = *(float4*)&ws[kk][tx * 8];
                float4 B1 = *(float4*)&ws[kk][tx * 8 + 4];
                float ar[8] = {A0.x,A0.y,A0.z,A0.w,A1.x,A1.y,A1.z,A1.w};
                float br[8] = {B0.x,B0.y,B0.z,B0.w,B1.x,B1.y,B1.z,B1.w};
                #pragma unroll
                for (int i = 0; i < 8; i++)
                    #pragma unroll
                    for (int j = 0; j < 8; j++)
                        acc[i][j] += ar[i] * br[j];
            }
        }

        float bb[8];
        #pragma unroll
        for (int j = 0; j < 8; j++) bb[j] = bias[nBase + tx * 8 + j];
        const int h  = (nBase + tx * 8) >> 6;
        const int ch = (nBase + tx * 8) & 63;

        int r0 = rowBase + ty * 8;
        int b_ = r0 / SEQ, s0 = r0 % SEQ;
        #pragma unroll
        for (int j = 0; j < 8; j++) {
            __align__(16) __half hb[8];
            #pragma unroll
            for (int i = 0; i < 8; i++)
                hb[i] = __float2half_rn(fmaxf(acc[i][j] + bb[j], 0.f));  // ReLU
            size_t base = ((size_t)(b_ * NHEAD + h) * HDIM + (ch + j)) * SEQ + s0;
            *(uint4*)&g_vt16[base] = *(uint4*)hb;
        }
        return;
    }

    // ================== Q/K: split-fp16 HMMA path ==================
    __half* xh = (__half*)smraw;
    __half* xl = (__half*)(smraw + 6144);
    __half* wh = (__half*)(smraw + 12288);
    __half* wl = (__half*)(smraw + 18432);

    const float* W    = (z == 0) ? wq : wk;
    const float* bias = (z == 0) ? bq : bk;
    __half* D         = (z == 0) ? g_q16 : g_k16;

    const int w = t >> 5, lane = t & 31;
    const int rowBase = blockIdx.y * 128;
    const int nBase   = blockIdx.x * 128;

    const uint32_t xh_b = smem_u32(xh), xl_b = smem_u32(xl);
    const uint32_t wh_b = smem_u32(wh), wl_b = smem_u32(wl);

    const int ar  = (lane & 7) + ((lane >> 3) & 1) * 8;
    const int akb = (lane >> 4) * 16;
    const uint32_t aoff = (uint32_t)((w * 16 + ar) * 48 + akb);
    const int bn  = (lane & 7) + ((lane >> 4) & 1) * 8;
    const int bkb = ((lane >> 3) & 1) * 16;
    uint32_t boff[8];
    #pragma unroll
    for (int jp = 0; jp < 8; jp++) boff[jp] = (uint32_t)((jp * 16 + bn) * 48 + bkb);

    float oc[16][4];
    #pragma unroll
    for (int j = 0; j < 16; j++) { oc[j][0]=0.f; oc[j][1]=0.f; oc[j][2]=0.f; oc[j][3]=0.f; }

    float4 xv[2]; float wvv[2][4];
    int xrow[2], xseg[2], wcol[2], wk4[2];
    #pragma unroll
    for (int p = 0; p < 2; p++) {
        int idx = t + p * 256;
        xrow[p] = idx >> 2; xseg[p] = idx & 3;
        wcol[p] = idx & 127; wk4[p] = (idx >> 7) * 4;
    }

    #pragma unroll
    for (int p = 0; p < 2; p++) {
        xv[p] = *(const float4*)&x[(size_t)(rowBase + xrow[p]) * IN_DIM + xseg[p] * 4];
        #pragma unroll
        for (int i = 0; i < 4; i++)
            wvv[p][i] = W[(size_t)(wk4[p] + i) * DMODEL + nBase + wcol[p]];
    }

    #pragma unroll 1
    for (int kc = 0; kc < 16; kc++) {
        __syncthreads();
        #pragma unroll
        for (int p = 0; p < 2; p++) {
            float vv[4] = {xv[p].x, xv[p].y, xv[p].z, xv[p].w};
            __align__(8) __half hs[4], ls[4];
            #pragma unroll
            for (int i = 0; i < 4; i++) {
                hs[i] = __float2half_rn(vv[i]);
                ls[i] = __float2half_rn(vv[i] - __half2float(hs[i]));
            }
            *(uint2*)&xh[xrow[p] * 24 + xseg[p] * 4] = *(uint2*)hs;
            *(uint2*)&xl[xrow[p] * 24 + xseg[p] * 4] = *(uint2*)ls;
            __align__(8) __half whs[4], wls[4];
            #pragma unroll
            for (int i = 0; i < 4; i++) {
                whs[i] = __float2half_rn(wvv[p][i]);
                wls[i] = __float2half_rn(wvv[p][i] - __half2float(whs[i]));
            }
            *(uint2*)&wh[wcol[p] * 24 + wk4[p]] = *(uint2*)whs;
            *(uint2*)&wl[wcol[p] * 24 + wk4[p]] = *(uint2*)wls;
        }
        __syncthreads();

        if (kc + 1 < 16) {
            const int k0n = (kc + 1) * 16;
            #pragma unroll
            for (int p = 0; p < 2; p++) {
                xv[p] = *(const float4*)&x[(size_t)(rowBase + xrow[p]) * IN_DIM + k0n + xseg[p] * 4];
                #pragma unroll
                for (int i = 0; i < 4; i++)
                    wvv[p][i] = W[(size_t)(k0n + wk4[p] + i) * DMODEL + nBase + wcol[p]];
            }
        }

        uint32_t ah[4], al[4];
        ldsm4(ah, xh_b + aoff);
        ldsm4(al, xl_b + aoff);
        #pragma unroll
        for (int jp = 0; jp < 8; jp++) {
            uint32_t bh4[4], bl4[4];
            ldsm4(bh4, wh_b + boff[jp]);
            ldsm4(bl4, wl_b + boff[jp]);
            mma16816(oc[2*jp],     ah, bh4);
            mma16816(oc[2*jp + 1], ah, bh4 + 2);
            mma16816(oc[2*jp],     ah, bl4);
            mma16816(oc[2*jp + 1], ah, bl4 + 2);
            mma16816(oc[2*jp],     al, bh4);
            mma16816(oc[2*jp + 1], al, bh4 + 2);
        }
    }

    const int c2 = (lane & 3) * 2;
    const int row0 = rowBase + w * 16 + (lane >> 2);
    const int row1 = row0 + 8;
    const int b0_ = row0 / SEQ, s0 = row0 - b0_ * SEQ;
    const int b1_ = row1 / SEQ, s1 = row1 - b1_ * SEQ;
    #pragma unroll
    for (int j = 0; j < 16; j++) {
        int col = nBase + j * 8 + c2;
        int h = col >> 6, ch = col & 63;
        float bb0 = bias[col], bb1 = bias[col + 1];
        __half2 v0 = __floats2half2_rn(oc[j][0] + bb0, oc[j][1] + bb1);
        __half2 v1 = __floats2half2_rn(oc[j][2] + bb0, oc[j][3] + bb1);
        *(__half2*)&D[((size_t)(b0_ * NHEAD + h) * SEQ + s0) * HDIM + ch] = v0;
        *(__half2*)&D[((size_t)(b1_ * NHEAD + h) * SEQ + s1) * HDIM + ch] = v1;
    }
}

// ---------------------------------------------------------------------------
// K2 fused: fp16 HMMA attention, two-phase, 3-stage cp.async ring with ONE
// __syncthreads per tile (cp target (kt+1)%3, stragglers read (kt-1)%3 —
// distinct mod 3), warp-uniform mask skip, streaming p stores (st.global.cs).
// ---------------------------------------------------------------------------
__global__ __launch_bounds__(256, 2) void attn_kernel(
    float* __restrict__ Pext, int use_ext, float* __restrict__ out)
{
    __shared__ __align__(16) __half sk[3][64*64];
    __shared__ __align__(16) __half sv[3][64*64];

    float* P = use_ext ? Pext : g_scores_fallback;
    const int tid = threadIdx.x, w = tid >> 5, lane = tid & 31;
    const int bh = blockIdx.y;
    const int qBase = blockIdx.x * 128;

    const int row0 = qBase + w * 16 + (lane >> 2);
    const int row1 = row0 + 8;
    const int c2   = (lane & 3) * 2;
    const int lo0 = (row0 / NJOINT) * NJOINT, hi0 = lo0 + NJOINT;
    const int lo1 = (row1 / NJOINT) * NJOINT, hi1 = lo1 + NJOINT;
    const int wrow = qBase + w * 16;
    const int loW = (wrow / NJOINT) * NJOINT;
    const int hiW = ((wrow + 15) / NJOINT) * NJOINT + NJOINT;

    const __half* q = g_q16 + (size_t)bh * SEQ * HDIM;
    const char* kB = (const char*)(g_k16 + (size_t)bh * SEQ * HDIM);
    const char* vB = (const char*)(g_vt16 + (size_t)bh * HDIM * SEQ);

    uint32_t qf[4][4];
    {
        int r0c = min(row0, SEQ - 1), r1c = min(row1, SEQ - 1);
        #pragma unroll
        for (int t = 0; t < 4; t++) {
            qf[t][0] = *(const uint32_t*)&q[(size_t)r0c * HDIM + t*16 + c2];
            qf[t][1] = *(const uint32_t*)&q[(size_t)r1c * HDIM + t*16 + c2];
            qf[t][2] = *(const uint32_t*)&q[(size_t)r0c * HDIM + t*16 + 8 + c2];
            qf[t][3] = *(const uint32_t*)&q[(size_t)r1c * HDIM + t*16 + 8 + c2];
        }
    }

    const uint32_t sk_b = smem_u32(sk), sv_b = smem_u32(sv);

    uint32_t dstoff[2]; uint32_t srcKoff[2], srcVoff[2];
    #pragma unroll
    for (int p = 0; p < 2; p++) {
        int i = tid + p * 256;
        int r = i >> 3, cb = (i & 7) * 16;
        dstoff[p]  = SW(r * 128 + cb);
        srcKoff[p] = r * 128 + cb;
        srcVoff[p] = r * (SEQ * 2) + cb;
    }
    const int lrow = lane & 7;
    const int lcb  = (lane >> 3) * 16;
    uint32_t lof[8];
    #pragma unroll
    for (int j = 0; j < 8; j++) lof[j] = SW((j * 8 + lrow) * 128 + lcb);

    float rsum0 = 0.f, rsum1 = 0.f;

    // ================= Phase A: rowsum only =================
    #pragma unroll
    for (int p = 0; p < 2; p++)
        cpasync16(sk_b + dstoff[p], kB + srcKoff[p]);
    cp_commit();

    int cur = 0;
    #pragma unroll 1
    for (int kt = 0; kt < 25; kt++) {
        const int k0 = kt * 64;
        const uint32_t cb_ = sk_b + cur * 8192;
        if (kt + 1 < 25) {
            int nxt = cur + 1; if (nxt == 3) nxt = 0;
            const uint32_t nb = sk_b + nxt * 8192;
            #pragma unroll
            for (int p = 0; p < 2; p++)
                cpasync16(nb + dstoff[p], kB + (kt + 1) * 8192 + srcKoff[p]);
            cp_commit();
            cp_wait1();
        } else cp_wait0();
        __syncthreads();

        const bool needMask = (k0 < hiW) && (k0 + 64 > loW);

        #pragma unroll
        for (int jp = 0; jp < 4; jp++) {
            uint32_t b0[8], b1[8];
            {
                uint32_t a = cb_ + lof[jp * 2];
                ldsm4(b0, a); ldsm4(b0 + 4, a ^ 64);
                uint32_t b = cb_ + lof[jp * 2 + 1];
                ldsm4(b1, b); ldsm4(b1 + 4, b ^ 64);
            }
            float c0[4] = {0.f,0.f,0.f,0.f}, c1[4] = {0.f,0.f,0.f,0.f};
            #pragma unroll
            for (int t = 0; t < 4; t++) {
                mma16816(c0, qf[t], b0 + 2*t);
                mma16816(c1, qf[t], b1 + 2*t);
            }
            if (needMask) {
                #pragma unroll
                for (int jj = 0; jj < 2; jj++) {
                    const float* cc = jj ? c1 : c0;
                    int ka = k0 + (jp * 2 + jj) * 8 + c2, kb2 = ka + 1;
                    bool a00 = (ka  < lo0) | (ka  >= hi0) | (ka  == row0);
                    bool a01 = (kb2 < lo0) | (kb2 >= hi0) | (kb2 == row0);
                    bool a10 = (ka  < lo1) | (ka  >= hi1) | (ka  == row1);
                    bool a11 = (kb2 < lo1) | (kb2 >= hi1) | (kb2 == row1);
                    rsum0 += (a00 ? __expf(cc[0] * 0.125f) : 0.f)
                           + (a01 ? __expf(cc[1] * 0.125f) : 0.f);
                    rsum1 += (a10 ? __expf(cc[2] * 0.125f) : 0.f)
                           + (a11 ? __expf(cc[3] * 0.125f) : 0.f);
                }
            } else {
                rsum0 += __expf(c0[0] * 0.125f) + __expf(c0[1] * 0.125f)
                       + __expf(c1[0] * 0.125f) + __expf(c1[1] * 0.125f);
                rsum1 += __expf(c0[2] * 0.125f) + __expf(c0[3] * 0.125f)
                       + __expf(c1[2] * 0.125f) + __expf(c1[3] * 0.125f);
            }
        }
        cur = cur + 1; if (cur == 3) cur = 0;
    }

    #pragma unroll
    for (int off = 1; off < 4; off <<= 1) {
        rsum0 += __shfl_xor_sync(0xffffffffu, rsum0, off);
        rsum1 += __shfl_xor_sync(0xffffffffu, rsum1, off);
    }
    const float inv0 = (row0 < SEQ) ? 1.f / rsum0 : 0.f;
    const float inv1 = (row1 < SEQ) ? 1.f / rsum1 : 0.f;

    float* prow0 = P + ((size_t)bh * SEQ + row0) * SEQ;
    float* prow1 = P + ((size_t)bh * SEQ + row1) * SEQ;

    float oc[8][4];
    #pragma unroll
    for (int j = 0; j < 8; j++) { oc[j][0]=0.f; oc[j][1]=0.f; oc[j][2]=0.f; oc[j][3]=0.f; }

    // phase-transition guard: stragglers of kt=24 still read sk[cur=0]
    __syncthreads();

    // ================= Phase B: recompute, write p, O += pV =================
    #pragma unroll
    for (int p = 0; p < 2; p++) {
        cpasync16(sk_b + dstoff[p], kB + srcKoff[p]);
        cpasync16(sv_b + dstoff[p], vB + srcVoff[p]);
    }
    cp_commit();

    cur = 0;
    #pragma unroll 1
    for (int kt = 0; kt < 25; kt++) {
        const int k0 = kt * 64;
        const uint32_t ckb = sk_b + cur * 8192;
        const uint32_t cvb = sv_b + cur * 8192;
        if (kt + 1 < 25) {
            int nxt = cur + 1; if (nxt == 3) nxt = 0;
            #pragma unroll
            for (int p = 0; p < 2; p++) {
                cpasync16(sk_b + nxt * 8192 + dstoff[p], kB + (kt + 1) * 8192 + srcKoff[p]);
                cpasync16(sv_b + nxt * 8192 + dstoff[p], vB + (kt + 1) * 128  + srcVoff[p]);
            }
            cp_commit();
            cp_wait1();
        } else cp_wait0();
        __syncthreads();

        const bool needMask = (k0 < hiW) && (k0 + 64 > loW);

        uint32_t pa[4][4];
        #pragma unroll
        for (int jp = 0; jp < 4; jp++) {
            uint32_t b0[8], b1[8];
            {
                uint32_t a = ckb + lof[jp * 2];
                ldsm4(b0, a); ldsm4(b0 + 4, a ^ 64);
                uint32_t b = ckb + lof[jp * 2 + 1];
                ldsm4(b1, b); ldsm4(b1 + 4, b ^ 64);
            }
            float c0[4] = {0.f,0.f,0.f,0.f}, c1[4] = {0.f,0.f,0.f,0.f};
            #pragma unroll
            for (int t = 0; t < 4; t++) {
                mma16816(c0, qf[t], b0 + 2*t);
                mma16816(c1, qf[t], b1 + 2*t);
            }
            if (needMask) {
                #pragma unroll
                for (int jj = 0; jj < 2; jj++) {
                    const float* cc = jj ? c1 : c0;
                    int ka = k0 + (jp * 2 + jj) * 8 + c2, kb2 = ka + 1;
                    bool a00 = (ka  < lo0) | (ka  >= hi0) | (ka  == row0);
                    bool a01 = (kb2 < lo0) | (kb2 >= hi0) | (kb2 == row0);
                    bool a10 = (ka  < lo1) | (ka  >= hi1) | (ka  == row1);
                    bool a11 = (kb2 < lo1) | (kb2 >= hi1) | (kb2 == row1);
                    float p00 = a00 ? __expf(cc[0] * 0.125f) * inv0 : 0.f;
                    float p01 = a01 ? __expf(cc[1] * 0.125f) * inv0 : 0.f;
                    float p10 = a10 ? __expf(cc[2] * 0.125f) * inv1 : 0.f;
                    float p11 = a11 ? __expf(cc[3] * 0.125f) * inv1 : 0.f;
                    if (row0 < SEQ) stg_cs2(&prow0[ka], p00, p01);
                    if (row1 < SEQ) stg_cs2(&prow1[ka], p10, p11);
                    __half2 h0 = __floats2half2_rn(p00, p01);
                    __half2 h1 = __floats2half2_rn(p10, p11);
                    pa[jp][jj * 2 + 0] = *(uint32_t*)&h0;
                    pa[jp][jj * 2 + 1] = *(uint32_t*)&h1;
                }
            } else {
                #pragma unroll
                for (int jj = 0; jj < 2; jj++) {
                    const float* cc = jj ? c1 : c0;
                    int ka = k0 + (jp * 2 + jj) * 8 + c2;
                    float p00 = __expf(cc[0] * 0.125f) * inv0;
                    float p01 = __expf(cc[1] * 0.125f) * inv0;
                    float p10 = __expf(cc[2] * 0.125f) * inv1;
                    float p11 = __expf(cc[3] * 0.125f) * inv1;
                    if (row0 < SEQ) stg_cs2(&prow0[ka], p00, p01);
                    if (row1 < SEQ) stg_cs2(&prow1[ka], p10, p11);
                    __half2 h0 = __floats2half2_rn(p00, p01);
                    __half2 h1 = __floats2half2_rn(p10, p11);
                    pa[jp][jj * 2 + 0] = *(uint32_t*)&h0;
                    pa[jp][jj * 2 + 1] = *(uint32_t*)&h1;
                }
            }
        }

        #pragma unroll
        for (int jp = 0; jp < 4; jp++) {
            uint32_t b0[8], b1[8];
            {
                uint32_t a = cvb + lof[jp * 2];
                ldsm4(b0, a); ldsm4(b0 + 4, a ^ 64);
                uint32_t b = cvb + lof[jp * 2 + 1];
                ldsm4(b1, b); ldsm4(b1 + 4, b ^ 64);
            }
            #pragma unroll
            for (int t = 0; t < 4; t++) {
                mma16816(oc[jp * 2],     pa[t], b0 + 2*t);
                mma16816(oc[jp * 2 + 1], pa[t], b1 + 2*t);
            }
        }
        cur = cur + 1; if (cur == 3) cur = 0;
    }

    const int b_ = bh >> 3, h_ = bh & 7;
    float* ob0 = out + ((size_t)b_ * SEQ + row0) * DMODEL + h_ * HDIM;
    float* ob1 = out + ((size_t)b_ * SEQ + row1) * DMODEL + h_ * HDIM;
    #pragma unroll
    for (int j = 0; j < 8; j++) {
        if (row0 < SEQ) *(float2*)&ob0[j * 8 + c2] = make_float2(oc[j][0], oc[j][1]);
        if (row1 < SEQ) *(float2*)&ob1[j * 8 + c2] = make_float2(oc[j][2], oc[j][3]);
    }
}

// ---------------------------------------------------------------------------
extern "C" void kernel_launch(void* const* d_in, const int* in_sizes, int n_in,
                              void* d_out, int out_size)
{
    const float* x  = (const float*)d_in[0];
    const float* wq = (const float*)d_in[1];
    const float* bq = (const float*)d_in[2];
    const float* wk = (const float*)d_in[3];
    const float* bk = (const float*)d_in[4];
    const float* wv = (const float*)d_in[5];
    const float* bv = (const float*)d_in[6];
    float* out = (float*)d_out;

    int use_ext = ((size_t)out_size >= OUT_ELEMS + PATT_ELEMS) ? 1 : 0;
    float* Pext = out + OUT_ELEMS;

    {   // K1: QKV -> fp16 (Q,K via HMMA; V via SIMT, transposed)
        dim3 grid(DMODEL / 128, (BATCH * SEQ) / 128, 3);
        qkv_kernel<<<grid, 256>>>(x, wq, bq, wk, bk, wv, bv);
    }
    {   // K2 fused: two-phase fp16 HMMA attention -> p (final) + out
        dim3 grid((SEQ + 127) / 128, BH);
        attn_kernel<<<grid, 256>>>(Pext, use_ext, out);
    }
}